// round 7
// baseline (speedup 1.0000x reference)
#include <cuda_runtime.h>
#include <cuda_bf16.h>
#include <math.h>

#define B_   4
#define N_   40000
#define E_   240000
#define CW_  128
#define ROWS_TOT (B_*N_)          // 160000
#define NC   (B_*N_*CW_)
#define NTILES 313                // ceil(40000/128)

// padded bf16 tile geometry: 128 rows x 136 cols, 272 B/row (68 u32)
#define IMG_U32 8704              // 34816 B
#define SLOT_U32 (2*IMG_U32)      // hi + lo = 69632 B

// ---- scratch ----
__device__ float g_x  [NC];
__device__ float g_xd [NC];
__device__ float g_gX [NC];
__device__ float g_gY [NC];
__device__ float g_gf [NC];
__device__ float g_h1 [NC];
__device__ float g_h2 [NC];
__device__ float g_spec[B_*128*128];
__device__ unsigned g_wimg[40*SLOT_U32];          // 36 static + 4 spec slots
__device__ unsigned g_eimg[B_*NTILES*SLOT_U32];   // evecs bf16 images (~87MB)
__device__ int g_rowptr[N_ + 1];
__device__ int g_cursor[N_];
__device__ int g_perm[E_];
__device__ int g_colss[E_];
__device__ float g_vxs[B_*E_];
__device__ float g_vys[B_*E_];

enum { EPI2_NONE = 0, EPI2_RELU = 1, EPI2_RES = 2, EPI2_GRAD = 3 };

// ===========================================================================
// helpers (baseline PTX: ldmatrix[.trans] + mma.sync + cp.async)
// ===========================================================================
__device__ __forceinline__ unsigned smem_u32(const void* p) {
    unsigned a;
    asm("{ .reg .u64 t; cvta.to.shared.u64 t, %1; cvt.u32.u64 %0, t; }"
        : "=r"(a) : "l"(p));
    return a;
}
__device__ __forceinline__ void ldsm4(unsigned* r, unsigned addr) {
    asm volatile("ldmatrix.sync.aligned.m8n8.x4.shared.b16 {%0,%1,%2,%3}, [%4];"
                 : "=r"(r[0]), "=r"(r[1]), "=r"(r[2]), "=r"(r[3]) : "r"(addr));
}
__device__ __forceinline__ void ldsm4t(unsigned* r, unsigned addr) {
    asm volatile("ldmatrix.sync.aligned.m8n8.x4.trans.shared.b16 {%0,%1,%2,%3}, [%4];"
                 : "=r"(r[0]), "=r"(r[1]), "=r"(r[2]), "=r"(r[3]) : "r"(addr));
}
__device__ __forceinline__ void mma_bf16(float* c, const unsigned* a,
                                         unsigned b0, unsigned b1) {
    asm volatile(
        "mma.sync.aligned.m16n8k16.row.col.f32.bf16.bf16.f32 "
        "{%0,%1,%2,%3}, {%4,%5,%6,%7}, {%8,%9}, {%0,%1,%2,%3};"
        : "+f"(c[0]), "+f"(c[1]), "+f"(c[2]), "+f"(c[3])
        : "r"(a[0]), "r"(a[1]), "r"(a[2]), "r"(a[3]), "r"(b0), "r"(b1));
}
__device__ __forceinline__ void cp16(unsigned saddr, const void* g) {
    asm volatile("cp.async.cg.shared.global [%0], [%1], 16;"
                 :: "r"(saddr), "l"(g));
}
#define CP_COMMIT() asm volatile("cp.async.commit_group;" ::: "memory")
#define CP_WAIT0()  asm volatile("cp.async.wait_group 0;" ::: "memory")

__device__ __forceinline__ unsigned pack_bf(float a, float b) {
    __nv_bfloat162 t = __floats2bfloat162_rn(a, b);
    return *reinterpret_cast<unsigned*>(&t);
}
__device__ __forceinline__ void split2(float a, float b, unsigned& h, unsigned& l) {
    float ah = __bfloat162float(__float2bfloat16_rn(a));
    float bh = __bfloat162float(__float2bfloat16_rn(b));
    h = pack_bf(a, b);
    l = pack_bf(a - ah, b - bh);
}

// ===========================================================================
// zero
// ===========================================================================
__global__ void zero_k(float4* __restrict__ p, int n4) {
    int i = blockIdx.x * blockDim.x + threadIdx.x;
    if (i < n4) p[i] = make_float4(0.f, 0.f, 0.f, 0.f);
}
__global__ void zero_i(int* __restrict__ p, int n) {
    int i = blockIdx.x * blockDim.x + threadIdx.x;
    if (i < n) p[i] = 0;
}

// ===========================================================================
// CSR build: hist -> scan -> perm -> value presort
// ===========================================================================
__global__ void hist_k(const int* __restrict__ rows, int* __restrict__ rowptr) {
    int e = blockIdx.x * blockDim.x + threadIdx.x;
    if (e < E_) atomicAdd(&rowptr[__ldg(rows + e) + 1], 1);
}
__global__ __launch_bounds__(1024) void scan_k(int* __restrict__ rowptr) {
    __shared__ int sums[1024];
    int t = threadIdx.x;
    const int PER = (N_ + 1023) / 1024;
    int base = 1 + t * PER;
    int s = 0;
    #pragma unroll 4
    for (int i = 0; i < PER; i++) {
        int idx = base + i;
        if (idx <= N_) s += rowptr[idx];
    }
    sums[t] = s;
    __syncthreads();
    for (int off = 1; off < 1024; off <<= 1) {
        int v = (t >= off) ? sums[t - off] : 0;
        __syncthreads();
        sums[t] += v;
        __syncthreads();
    }
    int run = (t > 0) ? sums[t - 1] : 0;
    #pragma unroll 4
    for (int i = 0; i < PER; i++) {
        int idx = base + i;
        if (idx <= N_) {
            run += rowptr[idx];
            rowptr[idx] = run;
        }
    }
    if (t == 0) rowptr[0] = 0;
}
__global__ void cursor_k(const int* __restrict__ rowptr, int* __restrict__ cur) {
    int r = blockIdx.x * blockDim.x + threadIdx.x;
    if (r < N_) cur[r] = rowptr[r];
}
__global__ void perm_k(const int* __restrict__ rows, int* __restrict__ cur,
                       int* __restrict__ perm) {
    int e = blockIdx.x * blockDim.x + threadIdx.x;
    if (e < E_) {
        int pos = atomicAdd(&cur[__ldg(rows + e)], 1);
        perm[pos] = e;
    }
}
__global__ void sortvals_k(const int* __restrict__ perm, const int* __restrict__ cols,
                           const float* __restrict__ gxv, const float* __restrict__ gyv,
                           int* __restrict__ colss, float* __restrict__ vxs,
                           float* __restrict__ vys) {
    int j = blockIdx.x * blockDim.x + threadIdx.x;
    if (j >= E_) return;
    int e = __ldg(perm + j);
    colss[j] = __ldg(cols + e);
    #pragma unroll
    for (int b = 0; b < B_; b++) {
        vxs[b * E_ + j] = __ldg(gxv + (long)b * E_ + e);
        vys[b * E_ + j] = __ldg(gyv + (long)b * E_ + e);
    }
}

// ===========================================================================
// gather SPMM (presorted values, no atomics)
// ===========================================================================
#define SG_ROWS 8
__global__ __launch_bounds__(128) void spmm_gather_k(
    const int* __restrict__ rowptr, const int* __restrict__ colss,
    const float* __restrict__ vxs, const float* __restrict__ vys,
    const float* __restrict__ xd, float* __restrict__ gX, float* __restrict__ gY)
{
    int b = blockIdx.y;
    int c = threadIdx.x;
    int r0 = blockIdx.x * SG_ROWS;
    const float* xb = xd + (long)b * N_ * 128;
    const float* vx = vxs + (long)b * E_;
    const float* vy = vys + (long)b * E_;
    float* oX = gX + (long)b * N_ * 128;
    float* oY = gY + (long)b * N_ * 128;
    #pragma unroll
    for (int rr = 0; rr < SG_ROWS; rr++) {
        int r = r0 + rr;
        int j    = __ldg(rowptr + r);
        int jend = __ldg(rowptr + r + 1);
        float ax = 0.f, ay = 0.f;
        for (; j + 1 < jend; j += 2) {
            int c0 = __ldg(colss + j), c1 = __ldg(colss + j + 1);
            float x0 = __ldg(xb + (long)c0 * 128 + c);
            float x1 = __ldg(xb + (long)c1 * 128 + c);
            ax += __ldg(vx + j) * x0 + __ldg(vx + j + 1) * x1;
            ay += __ldg(vy + j) * x0 + __ldg(vy + j + 1) * x1;
        }
        if (j < jend) {
            int c0 = __ldg(colss + j);
            float x0 = __ldg(xb + (long)c0 * 128 + c);
            ax += __ldg(vx + j) * x0;
            ay += __ldg(vy + j) * x0;
        }
        oX[(long)r * 128 + c] = ax;
        oY[(long)r * 128 + c] = ay;
    }
}

// ===========================================================================
// first / last
// ===========================================================================
__global__ __launch_bounds__(128) void first_k(
    const float* __restrict__ x_in, const float* __restrict__ w,
    const float* __restrict__ bias, float* __restrict__ x)
{
    __shared__ float sW[6 * 128];
    __shared__ float sB[128];
    __shared__ float sX[32 * 6];
    int tid = threadIdx.x;
    long m0 = (long)blockIdx.x * 32;
    for (int idx = tid; idx < 768; idx += 128) sW[idx] = __ldg(w + idx);
    sB[tid] = __ldg(bias + tid);
    for (int idx = tid; idx < 192; idx += 128) sX[idx] = __ldg(x_in + m0 * 6 + idx);
    __syncthreads();
    #pragma unroll 4
    for (int r = 0; r < 32; r++) {
        float a = sB[tid];
        #pragma unroll
        for (int t = 0; t < 6; t++) a += sX[r * 6 + t] * sW[t * 128 + tid];
        x[(m0 + r) * 128 + tid] = a;
    }
}
__global__ __launch_bounds__(128) void last_k(
    const float* __restrict__ x, const float* __restrict__ w,
    const float* __restrict__ bias, float* __restrict__ out)
{
    __shared__ float sX[32 * 128];
    __shared__ float sW[128 * 3];
    __shared__ float sB[3];
    int tid = threadIdx.x;
    long m0 = (long)blockIdx.x * 32;
    for (int idx = tid; idx < 384; idx += 128) sW[idx] = __ldg(w + idx);
    if (tid < 3) sB[tid] = __ldg(bias + tid);
    for (int idx = tid; idx < 1024; idx += 128)
        ((float4*)sX)[idx] = __ldg((const float4*)(x + m0 * 128) + idx);
    __syncthreads();
    if (tid < 96) {
        int r = tid / 3, c = tid % 3;
        float a = sB[c];
        #pragma unroll 8
        for (int k = 0; k < 128; k++) a += sX[r * 128 + k] * sW[k * 3 + c];
        out[(m0 + r) * 3 + c] = a;
    }
}

// ===========================================================================
// evecs image prep (once): bf16 hi/lo split, 272B-pitch tiles
// ===========================================================================
__global__ __launch_bounds__(256) void prep_evecs_k(
    const float* __restrict__ evecs, unsigned* __restrict__ eimg)
{
    int t = blockIdx.x, b = blockIdx.y;
    const float* Eb = evecs + (long)b * N_ * 128;
    unsigned* hi = eimg + (long)(b * NTILES + t) * SLOT_U32;
    unsigned* lo = hi + IMG_U32;
    int tid = threadIdx.x;
    for (int idx = tid; idx < 4096; idx += 256) {
        int rr = idx >> 5, qq = idx & 31;
        int grow = t * 128 + rr;
        float4 v = make_float4(0.f, 0.f, 0.f, 0.f);
        if (grow < N_) v = __ldg((const float4*)(Eb + (long)grow * 128) + qq);
        unsigned h0, l0, h1, l1;
        split2(v.x, v.y, h0, l0);
        split2(v.z, v.w, h1, l1);
        unsigned o = rr * 68 + qq * 2;
        hi[o] = h0; hi[o + 1] = h1;
        lo[o] = l0; lo[o + 1] = l1;
    }
}

// ===========================================================================
// W-image preps
// ===========================================================================
__device__ __forceinline__ void prep_w_body(const float* W, float s,
                                            unsigned* hi, unsigned* lo, int tid)
{
    for (int idx = tid; idx < 8192; idx += 256) {
        int n = idx >> 6, kp = idx & 63;
        int k = kp * 2;
        float v0 = __ldg(W + (k + 0) * 128 + n) * s;
        float v1 = __ldg(W + (k + 1) * 128 + n) * s;
        unsigned h, l;
        split2(v0, v1, h, l);
        hi[n * 68 + kp] = h;
        lo[n * 68 + kp] = l;
    }
}
// all 36 static slots in one launch: per iter i, 9 slots:
// 0:Are 1:Aim 2:-Aim 3:Are 4..6:mlp_w0 parts 7:mlp_w1 8:mlp_w2
__global__ __launch_bounds__(256) void prep_all_w_k(
    const float* __restrict__ A_re, const float* __restrict__ A_im,
    const float* __restrict__ w0, const float* __restrict__ w1,
    const float* __restrict__ w2, unsigned* __restrict__ wimg)
{
    int s = blockIdx.x;
    int i = s / 9, j = s % 9;
    const float* W;
    float sc = 1.f;
    switch (j) {
        case 0: W = A_re + (long)i * 16384; break;
        case 1: W = A_im + (long)i * 16384; break;
        case 2: W = A_im + (long)i * 16384; sc = -1.f; break;
        case 3: W = A_re + (long)i * 16384; break;
        case 4: W = w0 + (long)i * 49152; break;
        case 5: W = w0 + (long)i * 49152 + 16384; break;
        case 6: W = w0 + (long)i * 49152 + 32768; break;
        case 7: W = w1 + (long)i * 16384; break;
        default: W = w2 + (long)i * 16384; break;
    }
    unsigned* hi = wimg + (long)s * SLOT_U32;
    prep_w_body(W, sc, hi, hi + IMG_U32, threadIdx.x);
}
// per-iter spec slots (exp(-eval*dt) folded in); writes 4 slots at wimg base
__global__ __launch_bounds__(256) void prep_spec_k(
    const float* __restrict__ spec, const float* __restrict__ evals,
    const float* __restrict__ dt, unsigned* __restrict__ wimg)
{
    int b = blockIdx.x;
    const float* W  = spec  + (long)b * 16384;
    const float* ev = evals + b * 128;
    unsigned* hi = wimg + (long)b * SLOT_U32;
    unsigned* lo = hi + IMG_U32;
    int tid = threadIdx.x;
    for (int idx = tid; idx < 8192; idx += 256) {
        int n = idx >> 6, kp = idx & 63;
        int k = kp * 2;
        float d = __ldg(dt + n);
        float v0 = __ldg(W + (k + 0) * 128 + n) * expf(-__ldg(ev + k + 0) * d);
        float v1 = __ldg(W + (k + 1) * 128 + n) * expf(-__ldg(ev + k + 1) * d);
        unsigned h, l;
        split2(v0, v1, h, l);
        hi[n * 68 + kp] = h;
        lo[n * 68 + kp] = l;
    }
}

// ===========================================================================
// spectral forward via MMA: spec[b][kk][c] += sum_n E[n][kk]*(m*x)[n][c]
// both operands trans-ldmatrix from [n][*] tiles; bf16x3.
// block: 256 thr, warp grid 4(kk)x2(c); chunk = 1024 n rows (8 tiles).
// smem: Ehi|Elo|Xhi|Xlo = 4*34816
// ===========================================================================
#define SPECF_SMEM (4*34816)
__global__ __launch_bounds__(256, 1) void spec_fwd_mma(
    const unsigned* __restrict__ eimg, const float* __restrict__ x,
    const float* __restrict__ mass, float* __restrict__ spec)
{
    extern __shared__ char sb[];
    unsigned sbase = smem_u32(sb);
    int tid = threadIdx.x, wid = tid >> 5, lid = tid & 31;
    int b = blockIdx.y;
    int tile0 = blockIdx.x * 8;

    int q = lid >> 3, r = lid & 7;
    int mwarp = wid >> 1, nwarp = wid & 1;
    // trans-A (E^T): matrix q -> (n=(q>>1)*8+r, kk=(q&1)*8)
    int a_n = (q >> 1) * 8 + r, a_kk = (q & 1) * 8;
    // trans-B (X^T): matrix q -> (n=(q&1)*8+r, c=(q>>1)*8)
    int b_n = (q & 1) * 8 + r, b_c = (q >> 1) * 8;

    unsigned aoffb[2], boffb[4];
    #pragma unroll
    for (int mt = 0; mt < 2; mt++)
        aoffb[mt] = (unsigned)(a_n * 272 + (mwarp * 32 + mt * 16 + a_kk) * 2);
    #pragma unroll
    for (int np = 0; np < 4; np++)
        boffb[np] = (unsigned)(b_n * 272 + (nwarp * 64 + np * 16 + b_c) * 2);

    unsigned sE  = sbase, sEl = sbase + 34816u;
    unsigned sXh = sbase + 2u * 34816u, sXl = sbase + 3u * 34816u;

    float acc[2][8][4];
    #pragma unroll
    for (int mt = 0; mt < 2; mt++)
        #pragma unroll
        for (int nt = 0; nt < 8; nt++)
            #pragma unroll
            for (int j = 0; j < 4; j++) acc[mt][nt][j] = 0.f;

    const float* Xb = x    + (long)b * N_ * 128;
    const float* Mb = mass + (long)b * N_;

    for (int t = 0; t < 8; t++) {
        int tile = tile0 + t;
        if (tile >= NTILES) break;
        __syncthreads();
        // E images via cp.async
        {
            const uint4* src = (const uint4*)(eimg + (long)(b * NTILES + tile) * SLOT_U32);
            #pragma unroll 4
            for (int idx = tid; idx < 4352; idx += 256)
                cp16(sE + idx * 16u, src + idx);
        }
        CP_COMMIT();
        // X tile: load, scale by mass, split
        #pragma unroll 4
        for (int idx = tid; idx < 4096; idx += 256) {
            int rr = idx >> 5, qq = idx & 31;
            int grow = tile * 128 + rr;
            float4 v = make_float4(0.f, 0.f, 0.f, 0.f);
            if (grow < N_) {
                v = __ldg((const float4*)(Xb + (long)grow * 128) + qq);
                float m = __ldg(Mb + grow);
                v.x *= m; v.y *= m; v.z *= m; v.w *= m;
            }
            unsigned h0, l0, h1, l1;
            split2(v.x, v.y, h0, l0);
            split2(v.z, v.w, h1, l1);
            unsigned off = rr * 272 + qq * 8;
            *(uint2*)(sb + 2 * 34816 + off) = make_uint2(h0, h1);
            *(uint2*)(sb + 3 * 34816 + off) = make_uint2(l0, l1);
        }
        CP_WAIT0();
        __syncthreads();

        #pragma unroll
        for (int ks = 0; ks < 8; ks++) {
            unsigned kb = ks * 4352u;   // 16 n-rows * 272 B
            unsigned eh[2][4], el[2][4];
            #pragma unroll
            for (int mt = 0; mt < 2; mt++) {
                ldsm4t(eh[mt], sE  + aoffb[mt] + kb);
                ldsm4t(el[mt], sEl + aoffb[mt] + kb);
            }
            #pragma unroll
            for (int np = 0; np < 4; np++) {
                unsigned xh[4], xl[4];
                ldsm4t(xh, sXh + boffb[np] + kb);
                ldsm4t(xl, sXl + boffb[np] + kb);
                #pragma unroll
                for (int mt = 0; mt < 2; mt++) {
                    float* c0 = acc[mt][np * 2];
                    float* c1 = acc[mt][np * 2 + 1];
                    mma_bf16(c0, eh[mt], xh[0], xh[1]);
                    mma_bf16(c0, el[mt], xh[0], xh[1]);
                    mma_bf16(c0, eh[mt], xl[0], xl[1]);
                    mma_bf16(c1, eh[mt], xh[2], xh[3]);
                    mma_bf16(c1, el[mt], xh[2], xh[3]);
                    mma_bf16(c1, eh[mt], xl[2], xl[3]);
                }
            }
        }
    }

    // atomic finish into spec[b]
    float* Sb = spec + (long)b * 16384;
    int colg = (lid & 3) * 2;
    int rowg = lid >> 2;
    #pragma unroll
    for (int mt = 0; mt < 2; mt++)
        #pragma unroll
        for (int h = 0; h < 2; h++) {
            int kk = mwarp * 32 + mt * 16 + rowg + h * 8;
            #pragma unroll
            for (int nt = 0; nt < 8; nt++) {
                int c = nwarp * 64 + nt * 8 + colg;
                atomicAdd(Sb + kk * 128 + c,     acc[mt][nt][h * 2]);
                atomicAdd(Sb + kk * 128 + c + 1, acc[mt][nt][h * 2 + 1]);
            }
        }
}

// ===========================================================================
// mma.sync bf16x3 GEMM; optional pre-split A images (Aimg)
// ===========================================================================
template <int ND>
__global__ __launch_bounds__(256, 1) void gemm_mma(
    const float* __restrict__ A0, const float* __restrict__ A1,
    const float* __restrict__ A2, const unsigned* __restrict__ Aimg,
    const unsigned* __restrict__ wimg,
    int M, int num_in, int slot0, int pbs, int epi,
    const float* __restrict__ bias, const float* __restrict__ resid,
    const float* __restrict__ gXp, const float* __restrict__ gYp,
    float* __restrict__ C)
{
    extern __shared__ char sb[];
    unsigned sbase = smem_u32(sb);

    int tid = threadIdx.x, wid = tid >> 5, lid = tid & 31;
    int zb = blockIdx.y;
    long aoff = (long)zb * M * 128;
    int m0 = blockIdx.x * 128;

    float acc[ND][2][8][4];
    #pragma unroll
    for (int d = 0; d < ND; d++)
        #pragma unroll
        for (int mt = 0; mt < 2; mt++)
            #pragma unroll
            for (int nt = 0; nt < 8; nt++)
                #pragma unroll
                for (int j = 0; j < 4; j++) acc[d][mt][nt][j] = 0.f;

    const float* As[3] = {A0, A1, A2};

    int q = lid >> 3, r = lid & 7;
    int mwarp = wid >> 1, nwarp = wid & 1;
    int a_row_in = (q & 1) * 8 + r;
    int a_koff   = (q >> 1) * 8;
    int b_row_in = (q >> 1) * 8 + r;
    int b_koff   = (q & 1) * 8;

    unsigned sA  = sbase;
    unsigned sAl = sbase + 34816u;
    unsigned sW0 = sbase + 2u * 34816u;

    unsigned aoffb[2], boffb[4];
    #pragma unroll
    for (int mt = 0; mt < 2; mt++)
        aoffb[mt] = (unsigned)((mwarp * 32 + mt * 16 + a_row_in) * 272 + a_koff * 2);
    #pragma unroll
    for (int np = 0; np < 4; np++)
        boffb[np] = (unsigned)((nwarp * 64 + np * 16 + b_row_in) * 272 + b_koff * 2);

    for (int jin = 0; jin < num_in; jin++) {
        __syncthreads();
        #pragma unroll
        for (int d = 0; d < ND; d++) {
            int slot = slot0 + zb * pbs + jin * ND + d;
            const uint4* src = (const uint4*)(wimg + (long)slot * SLOT_U32);
            unsigned dst = sW0 + d * 69632u;
            #pragma unroll 4
            for (int idx = tid; idx < 4352; idx += 256)
                cp16(dst + idx * 16u, src + idx);
        }
        if (Aimg) {
            const uint4* src = (const uint4*)(Aimg + (long)(zb * NTILES + blockIdx.x) * SLOT_U32);
            #pragma unroll 4
            for (int idx = tid; idx < 4352; idx += 256)
                cp16(sA + idx * 16u, src + idx);
            CP_COMMIT();
        } else {
            CP_COMMIT();
            const float* A = As[jin] + aoff;
            #pragma unroll 4
            for (int idx = tid; idx < 4096; idx += 256) {
                int rr = idx >> 5, qq = idx & 31;
                int grow = m0 + rr;
                float4 v = make_float4(0.f, 0.f, 0.f, 0.f);
                if (grow < M) v = __ldg((const float4*)(A + (long)grow * 128) + qq);
                unsigned h0, l0, h1, l1;
                split2(v.x, v.y, h0, l0);
                split2(v.z, v.w, h1, l1);
                unsigned off = rr * 272 + qq * 8;
                *(uint2*)(sb + off)         = make_uint2(h0, h1);
                *(uint2*)(sb + 34816 + off) = make_uint2(l0, l1);
            }
        }
        CP_WAIT0();
        __syncthreads();

        #pragma unroll
        for (int ks = 0; ks < 8; ks++) {
            unsigned kb = ks * 32;
            unsigned ah[2][4], al[2][4];
            #pragma unroll
            for (int mt = 0; mt < 2; mt++) {
                ldsm4(ah[mt], sA  + aoffb[mt] + kb);
                ldsm4(al[mt], sAl + aoffb[mt] + kb);
            }
            #pragma unroll
            for (int d = 0; d < ND; d++) {
                unsigned wHi = sW0 + d * 69632u;
                unsigned wLo = wHi + 34816u;
                #pragma unroll
                for (int np = 0; np < 4; np++) {
                    unsigned bh[4], bl[4];
                    ldsm4(bh, wHi + boffb[np] + kb);
                    ldsm4(bl, wLo + boffb[np] + kb);
                    #pragma unroll
                    for (int mt = 0; mt < 2; mt++) {
                        float* c0 = acc[d][mt][np * 2];
                        float* c1 = acc[d][mt][np * 2 + 1];
                        mma_bf16(c0, ah[mt], bh[0], bh[1]);
                        mma_bf16(c0, al[mt], bh[0], bh[1]);
                        mma_bf16(c0, ah[mt], bl[0], bl[1]);
                        mma_bf16(c1, ah[mt], bh[2], bh[3]);
                        mma_bf16(c1, al[mt], bh[2], bh[3]);
                        mma_bf16(c1, ah[mt], bl[2], bl[3]);
                    }
                }
            }
        }
    }

    // epilogue
    int colg = (lid & 3) * 2;
    int rowg = lid >> 2;
    #pragma unroll
    for (int mt = 0; mt < 2; mt++) {
        #pragma unroll
        for (int h = 0; h < 2; h++) {
            int row = m0 + mwarp * 32 + mt * 16 + rowg + h * 8;
            if (row >= M) continue;
            long rbase = aoff + (long)row * 128;
            #pragma unroll
            for (int nt = 0; nt < 8; nt++) {
                int col = nwarp * 64 + nt * 8 + colg;
                float v0 = acc[0][mt][nt][h * 2];
                float v1 = acc[0][mt][nt][h * 2 + 1];
                float o0, o1;
                if (epi == EPI2_GRAD) {
                    float w0 = acc[1][mt][nt][h * 2];
                    float w1 = acc[1][mt][nt][h * 2 + 1];
                    float2 gx = __ldg((const float2*)(gXp + rbase + col));
                    float2 gy = __ldg((const float2*)(gYp + rbase + col));
                    o0 = tanhf(gx.x * v0 + gy.x * w0);
                    o1 = tanhf(gx.y * v1 + gy.y * w1);
                } else if (epi == EPI2_NONE) {
                    o0 = v0; o1 = v1;
                } else {
                    float2 bv = __ldg((const float2*)(bias + col));
                    o0 = v0 + bv.x; o1 = v1 + bv.y;
                    if (epi == EPI2_RELU) {
                        o0 = fmaxf(o0, 0.f); o1 = fmaxf(o1, 0.f);
                    } else {
                        float2 rv = __ldg((const float2*)(resid + rbase + col));
                        o0 += rv.x; o1 += rv.y;
                    }
                }
                *(float2*)(C + rbase + col) = make_float2(o0, o1);
            }
        }
    }
}

// ===========================================================================
extern "C" void kernel_launch(void* const* d_in, const int* in_sizes, int n_in,
                              void* d_out, int out_size)
{
    const float* x_in    = (const float*)d_in[0];
    const float* mass    = (const float*)d_in[1];
    const float* evals   = (const float*)d_in[2];
    const float* evecs   = (const float*)d_in[3];
    const int*   rows    = (const int*)  d_in[4];
    const int*   cols    = (const int*)  d_in[5];
    const float* gradX   = (const float*)d_in[6];
    const float* gradY   = (const float*)d_in[7];
    const float* w_first = (const float*)d_in[8];
    const float* b_first = (const float*)d_in[9];
    const float* dtim    = (const float*)d_in[10];
    const float* A_re    = (const float*)d_in[11];
    const float* A_im    = (const float*)d_in[12];
    const float* mlp_w0  = (const float*)d_in[13];
    const float* mlp_b0  = (const float*)d_in[14];
    const float* mlp_w1  = (const float*)d_in[15];
    const float* mlp_b1  = (const float*)d_in[16];
    const float* mlp_w2  = (const float*)d_in[17];
    const float* mlp_b2  = (const float*)d_in[18];
    const float* w_last  = (const float*)d_in[19];
    const float* b_last  = (const float*)d_in[20];
    float* out = (float*)d_out;

    float *x, *xd, *gX, *gY, *gf, *h1, *h2, *spec;
    float *vxs, *vys;
    unsigned *wimg, *eimg;
    int *rowptr, *cursor, *perm, *colss;
    cudaGetSymbolAddress((void**)&x,     g_x);
    cudaGetSymbolAddress((void**)&xd,    g_xd);
    cudaGetSymbolAddress((void**)&gX,    g_gX);
    cudaGetSymbolAddress((void**)&gY,    g_gY);
    cudaGetSymbolAddress((void**)&gf,    g_gf);
    cudaGetSymbolAddress((void**)&h1,    g_h1);
    cudaGetSymbolAddress((void**)&h2,    g_h2);
    cudaGetSymbolAddress((void**)&spec,  g_spec);
    cudaGetSymbolAddress((void**)&wimg,  g_wimg);
    cudaGetSymbolAddress((void**)&eimg,  g_eimg);
    cudaGetSymbolAddress((void**)&rowptr, g_rowptr);
    cudaGetSymbolAddress((void**)&cursor, g_cursor);
    cudaGetSymbolAddress((void**)&perm,   g_perm);
    cudaGetSymbolAddress((void**)&colss,  g_colss);
    cudaGetSymbolAddress((void**)&vxs,    g_vxs);
    cudaGetSymbolAddress((void**)&vys,    g_vys);

    const int SMEM1 = 2 * 34816 + 1 * 69632;   // 139,264
    const int SMEM2 = 2 * 34816 + 2 * 69632;   // 208,896
    cudaFuncSetAttribute(gemm_mma<1>, cudaFuncAttributeMaxDynamicSharedMemorySize, SMEM1);
    cudaFuncSetAttribute(gemm_mma<2>, cudaFuncAttributeMaxDynamicSharedMemorySize, SMEM2);
    cudaFuncSetAttribute(spec_fwd_mma, cudaFuncAttributeMaxDynamicSharedMemorySize, SPECF_SMEM);

    const float* nullf = nullptr;
    const unsigned* nullu = nullptr;

    // ---- one-time preps ----
    zero_i<<<(N_ + 1 + 255) / 256, 256>>>(rowptr, N_ + 1);
    hist_k<<<(E_ + 255) / 256, 256>>>(rows, rowptr);
    scan_k<<<1, 1024>>>(rowptr);
    cursor_k<<<(N_ + 255) / 256, 256>>>(rowptr, cursor);
    perm_k<<<(E_ + 255) / 256, 256>>>(rows, cursor, perm);
    sortvals_k<<<(E_ + 255) / 256, 256>>>(perm, cols, gradX, gradY, colss, vxs, vys);
    prep_evecs_k<<<dim3(NTILES, B_), 256>>>(evecs, eimg);
    prep_all_w_k<<<36, 256>>>(A_re, A_im, mlp_w0, mlp_w1, mlp_w2, wimg);

    first_k<<<ROWS_TOT / 32, 128>>>(x_in, w_first, b_first, x);

    for (int i = 0; i < 4; i++) {
        // --- spectral diffusion ---
        zero_k<<<64, 256>>>((float4*)spec, B_ * 128 * 128 / 4);
        spec_fwd_mma<<<dim3(40, B_), 256, SPECF_SMEM>>>(eimg, x, mass, spec);
        prep_spec_k<<<4, 256>>>(spec, evals, dtim + i * CW_,
                                wimg + 36 * (long)SLOT_U32);
        gemm_mma<1><<<dim3(NTILES, B_), 256, SMEM1>>>(
            nullf, nullf, nullf, eimg, wimg, N_, 1, 36, 1, EPI2_NONE,
            nullf, nullf, nullf, nullf, xd);

        // --- sparse gradients (CSR gather) ---
        spmm_gather_k<<<dim3(N_ / SG_ROWS, B_), 128>>>(
            rowptr, colss, vxs, vys, xd, gX, gY);

        // --- rotation + tanh gradient features ---
        gemm_mma<2><<<dim3(ROWS_TOT / 128, 1), 256, SMEM2>>>(
            gX, gY, nullf, nullu, wimg, ROWS_TOT, 2, i * 9, 0, EPI2_GRAD,
            nullf, nullf, gX, gY, gf);

        // --- MiniMLP + residual ---
        gemm_mma<1><<<dim3(ROWS_TOT / 128, 1), 256, SMEM1>>>(
            x, xd, gf, nullu, wimg, ROWS_TOT, 3, i * 9 + 4, 0, EPI2_RELU,
            mlp_b0 + i * CW_, nullf, nullf, nullf, h1);
        gemm_mma<1><<<dim3(ROWS_TOT / 128, 1), 256, SMEM1>>>(
            h1, nullf, nullf, nullu, wimg, ROWS_TOT, 1, i * 9 + 7, 0, EPI2_RELU,
            mlp_b1 + i * CW_, nullf, nullf, nullf, h2);
        gemm_mma<1><<<dim3(ROWS_TOT / 128, 1), 256, SMEM1>>>(
            h2, nullf, nullf, nullu, wimg, ROWS_TOT, 1, i * 9 + 8, 0, EPI2_RES,
            mlp_b2 + i * CW_, x, nullf, nullf, x);
    }

    last_k<<<ROWS_TOT / 32, 128>>>(x, w_last, b_last, out);
}

// round 8
// speedup vs baseline: 1.3962x; 1.3962x over previous
#include <cuda_runtime.h>
#include <cuda_bf16.h>
#include <math.h>

#define B_   4
#define N_   40000
#define E_   240000
#define CW_  128
#define ROWS_TOT (B_*N_)          // 160000
#define NC   (B_*N_*CW_)

// padded bf16 image: 128 rows x 136 k-cols, 272 B/row
#define IMG_U32 8704              // 34816 B
#define SLOT_U32 (2*IMG_U32)      // hi + lo = 69632 B

// ---- scratch ----
__device__ float g_x  [NC];
__device__ float g_xd [NC];
__device__ float g_gX [NC];
__device__ float g_gY [NC];
__device__ float g_gf [NC];
__device__ float g_h1 [NC];
__device__ float g_h2 [NC];
__device__ float g_spec[B_*128*128];
__device__ unsigned g_wimg[40*SLOT_U32];   // 36 static + 4 spec slots
__device__ int g_rowptr[N_ + 1];
__device__ int g_cursor[N_];
__device__ int g_perm[E_];
__device__ int g_colss[E_];
__device__ float g_vxs[B_*E_];
__device__ float g_vys[B_*E_];

enum { EPI2_NONE = 0, EPI2_RELU = 1, EPI2_RES = 2, EPI2_GRAD = 3 };

// ===========================================================================
// helpers
// ===========================================================================
__device__ __forceinline__ unsigned smem_u32(const void* p) {
    unsigned a;
    asm("{ .reg .u64 t; cvta.to.shared.u64 t, %1; cvt.u32.u64 %0, t; }"
        : "=r"(a) : "l"(p));
    return a;
}
__device__ __forceinline__ void ldsm4(unsigned* r, unsigned addr) {
    asm volatile("ldmatrix.sync.aligned.m8n8.x4.shared.b16 {%0,%1,%2,%3}, [%4];"
                 : "=r"(r[0]), "=r"(r[1]), "=r"(r[2]), "=r"(r[3]) : "r"(addr));
}
__device__ __forceinline__ void mma_bf16(float* c, const unsigned* a,
                                         unsigned b0, unsigned b1) {
    asm volatile(
        "mma.sync.aligned.m16n8k16.row.col.f32.bf16.bf16.f32 "
        "{%0,%1,%2,%3}, {%4,%5,%6,%7}, {%8,%9}, {%0,%1,%2,%3};"
        : "+f"(c[0]), "+f"(c[1]), "+f"(c[2]), "+f"(c[3])
        : "r"(a[0]), "r"(a[1]), "r"(a[2]), "r"(a[3]), "r"(b0), "r"(b1));
}
__device__ __forceinline__ void cp16(unsigned saddr, const void* g) {
    asm volatile("cp.async.cg.shared.global [%0], [%1], 16;"
                 :: "r"(saddr), "l"(g));
}
#define CP_COMMIT() asm volatile("cp.async.commit_group;" ::: "memory")
#define CP_WAIT0()  asm volatile("cp.async.wait_group 0;" ::: "memory")

__device__ __forceinline__ unsigned pack_bf(float a, float b) {
    __nv_bfloat162 t = __floats2bfloat162_rn(a, b);
    return *reinterpret_cast<unsigned*>(&t);
}
__device__ __forceinline__ void split2(float a, float b, unsigned& h, unsigned& l) {
    float ah = __bfloat162float(__float2bfloat16_rn(a));
    float bh = __bfloat162float(__float2bfloat16_rn(b));
    h = pack_bf(a, b);
    l = pack_bf(a - ah, b - bh);
}

// ===========================================================================
// zero
// ===========================================================================
__global__ void zero_k(float4* __restrict__ p, int n4) {
    int i = blockIdx.x * blockDim.x + threadIdx.x;
    if (i < n4) p[i] = make_float4(0.f, 0.f, 0.f, 0.f);
}
__global__ void zero_i(int* __restrict__ p, int n) {
    int i = blockIdx.x * blockDim.x + threadIdx.x;
    if (i < n) p[i] = 0;
}

// ===========================================================================
// CSR build: hist -> scan -> perm -> value presort
// ===========================================================================
__global__ void hist_k(const int* __restrict__ rows, int* __restrict__ rowptr) {
    int e = blockIdx.x * blockDim.x + threadIdx.x;
    if (e < E_) atomicAdd(&rowptr[__ldg(rows + e) + 1], 1);
}
__global__ __launch_bounds__(1024) void scan_k(int* __restrict__ rowptr) {
    __shared__ int sums[1024];
    int t = threadIdx.x;
    const int PER = (N_ + 1023) / 1024;
    int base = 1 + t * PER;
    int s = 0;
    #pragma unroll 4
    for (int i = 0; i < PER; i++) {
        int idx = base + i;
        if (idx <= N_) s += rowptr[idx];
    }
    sums[t] = s;
    __syncthreads();
    for (int off = 1; off < 1024; off <<= 1) {
        int v = (t >= off) ? sums[t - off] : 0;
        __syncthreads();
        sums[t] += v;
        __syncthreads();
    }
    int run = (t > 0) ? sums[t - 1] : 0;
    #pragma unroll 4
    for (int i = 0; i < PER; i++) {
        int idx = base + i;
        if (idx <= N_) {
            run += rowptr[idx];
            rowptr[idx] = run;
        }
    }
    if (t == 0) rowptr[0] = 0;
}
__global__ void cursor_k(const int* __restrict__ rowptr, int* __restrict__ cur) {
    int r = blockIdx.x * blockDim.x + threadIdx.x;
    if (r < N_) cur[r] = rowptr[r];
}
__global__ void perm_k(const int* __restrict__ rows, int* __restrict__ cur,
                       int* __restrict__ perm) {
    int e = blockIdx.x * blockDim.x + threadIdx.x;
    if (e < E_) {
        int pos = atomicAdd(&cur[__ldg(rows + e)], 1);
        perm[pos] = e;
    }
}
__global__ void sortvals_k(const int* __restrict__ perm, const int* __restrict__ cols,
                           const float* __restrict__ gxv, const float* __restrict__ gyv,
                           int* __restrict__ colss, float* __restrict__ vxs,
                           float* __restrict__ vys) {
    int j = blockIdx.x * blockDim.x + threadIdx.x;
    if (j >= E_) return;
    int e = __ldg(perm + j);
    colss[j] = __ldg(cols + e);
    #pragma unroll
    for (int b = 0; b < B_; b++) {
        vxs[b * E_ + j] = __ldg(gxv + (long)b * E_ + e);
        vys[b * E_ + j] = __ldg(gyv + (long)b * E_ + e);
    }
}

// ===========================================================================
// gather SPMM (presorted values, no atomics)
// ===========================================================================
#define SG_ROWS 8
__global__ __launch_bounds__(128) void spmm_gather_k(
    const int* __restrict__ rowptr, const int* __restrict__ colss,
    const float* __restrict__ vxs, const float* __restrict__ vys,
    const float* __restrict__ xd, float* __restrict__ gX, float* __restrict__ gY)
{
    int b = blockIdx.y;
    int c = threadIdx.x;
    int r0 = blockIdx.x * SG_ROWS;
    const float* xb = xd + (long)b * N_ * 128;
    const float* vx = vxs + (long)b * E_;
    const float* vy = vys + (long)b * E_;
    float* oX = gX + (long)b * N_ * 128;
    float* oY = gY + (long)b * N_ * 128;
    #pragma unroll
    for (int rr = 0; rr < SG_ROWS; rr++) {
        int r = r0 + rr;
        int j    = __ldg(rowptr + r);
        int jend = __ldg(rowptr + r + 1);
        float ax = 0.f, ay = 0.f;
        for (; j + 1 < jend; j += 2) {
            int c0 = __ldg(colss + j), c1 = __ldg(colss + j + 1);
            float x0 = __ldg(xb + (long)c0 * 128 + c);
            float x1 = __ldg(xb + (long)c1 * 128 + c);
            ax += __ldg(vx + j) * x0 + __ldg(vx + j + 1) * x1;
            ay += __ldg(vy + j) * x0 + __ldg(vy + j + 1) * x1;
        }
        if (j < jend) {
            int c0 = __ldg(colss + j);
            float x0 = __ldg(xb + (long)c0 * 128 + c);
            ax += __ldg(vx + j) * x0;
            ay += __ldg(vy + j) * x0;
        }
        oX[(long)r * 128 + c] = ax;
        oY[(long)r * 128 + c] = ay;
    }
}

// ===========================================================================
// first / last
// ===========================================================================
__global__ __launch_bounds__(128) void first_k(
    const float* __restrict__ x_in, const float* __restrict__ w,
    const float* __restrict__ bias, float* __restrict__ x)
{
    __shared__ float sW[6 * 128];
    __shared__ float sB[128];
    __shared__ float sX[32 * 6];
    int tid = threadIdx.x;
    long m0 = (long)blockIdx.x * 32;
    for (int idx = tid; idx < 768; idx += 128) sW[idx] = __ldg(w + idx);
    sB[tid] = __ldg(bias + tid);
    for (int idx = tid; idx < 192; idx += 128) sX[idx] = __ldg(x_in + m0 * 6 + idx);
    __syncthreads();
    #pragma unroll 4
    for (int r = 0; r < 32; r++) {
        float a = sB[tid];
        #pragma unroll
        for (int t = 0; t < 6; t++) a += sX[r * 6 + t] * sW[t * 128 + tid];
        x[(m0 + r) * 128 + tid] = a;
    }
}
__global__ __launch_bounds__(128) void last_k(
    const float* __restrict__ x, const float* __restrict__ w,
    const float* __restrict__ bias, float* __restrict__ out)
{
    __shared__ float sX[32 * 128];
    __shared__ float sW[128 * 3];
    __shared__ float sB[3];
    int tid = threadIdx.x;
    long m0 = (long)blockIdx.x * 32;
    for (int idx = tid; idx < 384; idx += 128) sW[idx] = __ldg(w + idx);
    if (tid < 3) sB[tid] = __ldg(bias + tid);
    for (int idx = tid; idx < 1024; idx += 128)
        ((float4*)sX)[idx] = __ldg((const float4*)(x + m0 * 128) + idx);
    __syncthreads();
    if (tid < 96) {
        int r = tid / 3, c = tid % 3;
        float a = sB[c];
        #pragma unroll 8
        for (int k = 0; k < 128; k++) a += sX[r * 128 + k] * sW[k * 3 + c];
        out[(m0 + r) * 3 + c] = a;
    }
}

// ===========================================================================
// spectral forward (FFMA outer-product reduction — R6 version)
// ===========================================================================
#define SF_TS 16
__global__ __launch_bounds__(256) void spec_fwd_k(
    const float* __restrict__ evecs, const float* __restrict__ x,
    const float* __restrict__ mass, float* __restrict__ spec, int chunk)
{
    __shared__ float sE[SF_TS][128];
    __shared__ float sX[SF_TS][128];
    int b  = blockIdx.y;
    int n0 = blockIdx.x * chunk;
    int n1 = min(n0 + chunk, N_);
    int tid = threadIdx.x;
    int cg = tid & 15, kg = tid >> 4;
    int k0 = kg * 8, c0 = cg * 8;
    float acc[8][8];
    #pragma unroll
    for (int i = 0; i < 8; i++)
        #pragma unroll
        for (int j = 0; j < 8; j++) acc[i][j] = 0.f;

    const float* Eb = evecs + (long)b * N_ * 128;
    const float* Xb = x     + (long)b * N_ * 128;
    const float* Mb = mass  + (long)b * N_;

    for (int nt = n0; nt < n1; nt += SF_TS) {
        for (int idx = tid; idx < SF_TS * 32; idx += 256) {
            int r = idx >> 5, q = idx & 31;
            int n = nt + r;
            float4 e4 = make_float4(0.f, 0.f, 0.f, 0.f);
            float4 x4 = make_float4(0.f, 0.f, 0.f, 0.f);
            if (n < n1) {
                e4 = __ldg((const float4*)(Eb + (long)n * 128) + q);
                float m = __ldg(Mb + n);
                x4 = __ldg((const float4*)(Xb + (long)n * 128) + q);
                x4.x *= m; x4.y *= m; x4.z *= m; x4.w *= m;
            }
            ((float4*)sE[r])[q] = e4;
            ((float4*)sX[r])[q] = x4;
        }
        __syncthreads();
        #pragma unroll 4
        for (int t = 0; t < SF_TS; t++) {
            float4 ea = *(const float4*)&sE[t][k0];
            float4 eb = *(const float4*)&sE[t][k0 + 4];
            float4 xa = *(const float4*)&sX[t][c0];
            float4 xb = *(const float4*)&sX[t][c0 + 4];
            float e[8] = {ea.x, ea.y, ea.z, ea.w, eb.x, eb.y, eb.z, eb.w};
            float v[8] = {xa.x, xa.y, xa.z, xa.w, xb.x, xb.y, xb.z, xb.w};
            #pragma unroll
            for (int i = 0; i < 8; i++)
                #pragma unroll
                for (int j = 0; j < 8; j++) acc[i][j] += e[i] * v[j];
        }
        __syncthreads();
    }
    float* Sb = spec + (long)b * 128 * 128;
    #pragma unroll
    for (int i = 0; i < 8; i++)
        #pragma unroll
        for (int j = 0; j < 8; j++)
            atomicAdd(Sb + (long)(k0 + i) * 128 + (c0 + j), acc[i][j]);
}

// ===========================================================================
// W-image preps
// ===========================================================================
__device__ __forceinline__ void prep_w_body(const float* W, float s,
                                            unsigned* hi, unsigned* lo, int tid)
{
    for (int idx = tid; idx < 8192; idx += 256) {
        int n = idx >> 6, kp = idx & 63;
        int k = kp * 2;
        float v0 = __ldg(W + (k + 0) * 128 + n) * s;
        float v1 = __ldg(W + (k + 1) * 128 + n) * s;
        unsigned h, l;
        split2(v0, v1, h, l);
        hi[n * 68 + kp] = h;
        lo[n * 68 + kp] = l;
    }
}
// all 36 static slots in one launch; per iter i, 9 slots:
// 0:Are 1:Aim 2:-Aim 3:Are 4..6:mlp_w0 parts 7:mlp_w1 8:mlp_w2
__global__ __launch_bounds__(256) void prep_all_w_k(
    const float* __restrict__ A_re, const float* __restrict__ A_im,
    const float* __restrict__ w0, const float* __restrict__ w1,
    const float* __restrict__ w2, unsigned* __restrict__ wimg)
{
    int s = blockIdx.x;
    int i = s / 9, j = s % 9;
    const float* W;
    float sc = 1.f;
    switch (j) {
        case 0: W = A_re + (long)i * 16384; break;
        case 1: W = A_im + (long)i * 16384; break;
        case 2: W = A_im + (long)i * 16384; sc = -1.f; break;
        case 3: W = A_re + (long)i * 16384; break;
        case 4: W = w0 + (long)i * 49152; break;
        case 5: W = w0 + (long)i * 49152 + 16384; break;
        case 6: W = w0 + (long)i * 49152 + 32768; break;
        case 7: W = w1 + (long)i * 16384; break;
        default: W = w2 + (long)i * 16384; break;
    }
    unsigned* hi = wimg + (long)s * SLOT_U32;
    prep_w_body(W, sc, hi, hi + IMG_U32, threadIdx.x);
}
// per-iter spec slots (exp(-eval*dt) folded); grid (4 batches, 8 parts)
__global__ __launch_bounds__(256) void prep_spec_k(
    const float* __restrict__ spec, const float* __restrict__ evals,
    const float* __restrict__ dt, unsigned* __restrict__ wimg)
{
    int b = blockIdx.x, part = blockIdx.y;
    const float* W  = spec  + (long)b * 16384;
    const float* ev = evals + b * 128;
    unsigned* hi = wimg + (long)b * SLOT_U32;
    unsigned* lo = hi + IMG_U32;
    int end = (part + 1) * 1024;
    for (int idx = part * 1024 + threadIdx.x; idx < end; idx += 256) {
        int n = idx >> 6, kp = idx & 63;
        int k = kp * 2;
        float d = __ldg(dt + n);
        float v0 = __ldg(W + (k + 0) * 128 + n) * expf(-__ldg(ev + k + 0) * d);
        float v1 = __ldg(W + (k + 1) * 128 + n) * expf(-__ldg(ev + k + 1) * d);
        unsigned h, l;
        split2(v0, v1, h, l);
        hi[n * 68 + kp] = h;
        lo[n * 68 + kp] = l;
    }
}

// ===========================================================================
// mma.sync bf16x3 GEMM, tileable M (TM=64 -> 2 CTA/SM for ND=1)
// smem: A hi|lo (TM*272 each) | ND x W (hi|lo, 69632 each)
// ===========================================================================
template <int ND, int TM>
__global__ __launch_bounds__(256, (TM == 64 ? 2 : 1)) void gemm_mma(
    const float* __restrict__ A0, const float* __restrict__ A1,
    const float* __restrict__ A2, const unsigned* __restrict__ wimg,
    int M, int num_in, int slot0, int pbs, int epi,
    const float* __restrict__ bias, const float* __restrict__ resid,
    const float* __restrict__ gXp, const float* __restrict__ gYp,
    float* __restrict__ C)
{
    constexpr int MWN  = (TM == 128) ? 2 : 4;   // warps along N
    constexpr int NCW  = 128 / MWN;             // cols per warp (64 / 32)
    constexpr int NB   = NCW / 16;              // ldsm B groups (4 / 2)
    constexpr unsigned AIMG = TM * 272u;        // bytes per A image

    extern __shared__ char sb[];
    unsigned sbase = smem_u32(sb);

    int tid = threadIdx.x, wid = tid >> 5, lid = tid & 31;
    int zb = blockIdx.y;
    long aoff = (long)zb * M * 128;
    int m0 = blockIdx.x * TM;

    float acc[ND][2][NB * 2][4];
    #pragma unroll
    for (int d = 0; d < ND; d++)
        #pragma unroll
        for (int mt = 0; mt < 2; mt++)
            #pragma unroll
            for (int nt = 0; nt < NB * 2; nt++)
                #pragma unroll
                for (int j = 0; j < 4; j++) acc[d][mt][nt][j] = 0.f;

    const float* As[3] = {A0, A1, A2};

    int q = lid >> 3, r = lid & 7;
    int mwarp = wid / MWN, nwarp = wid % MWN;
    int a_row_in = (q & 1) * 8 + r;
    int a_koff   = (q >> 1) * 8;
    int b_row_in = (q >> 1) * 8 + r;
    int b_koff   = (q & 1) * 8;

    unsigned sA  = sbase;
    unsigned sAl = sbase + AIMG;
    unsigned sW0 = sbase + 2u * AIMG;

    unsigned aoffb[2], boffb[NB];
    #pragma unroll
    for (int mt = 0; mt < 2; mt++)
        aoffb[mt] = (unsigned)((mwarp * 32 + mt * 16 + a_row_in) * 272 + a_koff * 2);
    #pragma unroll
    for (int np = 0; np < NB; np++)
        boffb[np] = (unsigned)((nwarp * NCW + np * 16 + b_row_in) * 272 + b_koff * 2);

    for (int jin = 0; jin < num_in; jin++) {
        __syncthreads();
        // async-copy ND W slots (hi+lo contiguous)
        #pragma unroll
        for (int d = 0; d < ND; d++) {
            int slot = slot0 + zb * pbs + jin * ND + d;
            const uint4* src = (const uint4*)(wimg + (long)slot * SLOT_U32);
            unsigned dst = sW0 + d * 69632u;
            #pragma unroll 4
            for (int idx = tid; idx < 4352; idx += 256)
                cp16(dst + idx * 16u, src + idx);
        }
        CP_COMMIT();
        // load + split A tile
        const float* A = As[jin] + aoff;
        #pragma unroll 4
        for (int idx = tid; idx < TM * 32; idx += 256) {
            int rr = idx >> 5, qq = idx & 31;
            int grow = m0 + rr;
            float4 v = make_float4(0.f, 0.f, 0.f, 0.f);
            if (grow < M) v = __ldg((const float4*)(A + (long)grow * 128) + qq);
            unsigned h0, l0, h1, l1;
            split2(v.x, v.y, h0, l0);
            split2(v.z, v.w, h1, l1);
            unsigned off = rr * 272 + qq * 8;
            *(uint2*)(sb + off)        = make_uint2(h0, h1);
            *(uint2*)(sb + AIMG + off) = make_uint2(l0, l1);
        }
        CP_WAIT0();
        __syncthreads();

        #pragma unroll
        for (int ks = 0; ks < 8; ks++) {
            unsigned kb = ks * 32;
            unsigned ah[2][4], al[2][4];
            #pragma unroll
            for (int mt = 0; mt < 2; mt++) {
                ldsm4(ah[mt], sA  + aoffb[mt] + kb);
                ldsm4(al[mt], sAl + aoffb[mt] + kb);
            }
            #pragma unroll
            for (int d = 0; d < ND; d++) {
                unsigned wHi = sW0 + d * 69632u;
                unsigned wLo = wHi + 34816u;
                #pragma unroll
                for (int np = 0; np < NB; np++) {
                    unsigned bh[4], bl[4];
                    ldsm4(bh, wHi + boffb[np] + kb);
                    ldsm4(bl, wLo + boffb[np] + kb);
                    #pragma unroll
                    for (int mt = 0; mt < 2; mt++) {
                        float* c0 = acc[d][mt][np * 2];
                        float* c1 = acc[d][mt][np * 2 + 1];
                        mma_bf16(c0, ah[mt], bh[0], bh[1]);
                        mma_bf16(c0, al[mt], bh[0], bh[1]);
                        mma_bf16(c0, ah[mt], bl[0], bl[1]);
                        mma_bf16(c1, ah[mt], bh[2], bh[3]);
                        mma_bf16(c1, al[mt], bh[2], bh[3]);
                        mma_bf16(c1, ah[mt], bl[2], bl[3]);
                    }
                }
            }
        }
    }

    // epilogue
    int colg = (lid & 3) * 2;
    int rowg = lid >> 2;
    #pragma unroll
    for (int mt = 0; mt < 2; mt++) {
        #pragma unroll
        for (int h = 0; h < 2; h++) {
            int row = m0 + mwarp * 32 + mt * 16 + rowg + h * 8;
            if (row >= M) continue;
            long rbase = aoff + (long)row * 128;
            #pragma unroll
            for (int nt = 0; nt < NB * 2; nt++) {
                int col = nwarp * NCW + nt * 8 + colg;
                float v0 = acc[0][mt][nt][h * 2];
                float v1 = acc[0][mt][nt][h * 2 + 1];
                float o0, o1;
                if (epi == EPI2_GRAD) {
                    float w0 = acc[ND - 1][mt][nt][h * 2];
                    float w1 = acc[ND - 1][mt][nt][h * 2 + 1];
                    float2 gx = __ldg((const float2*)(gXp + rbase + col));
                    float2 gy = __ldg((const float2*)(gYp + rbase + col));
                    o0 = tanhf(gx.x * v0 + gy.x * w0);
                    o1 = tanhf(gx.y * v1 + gy.y * w1);
                } else if (epi == EPI2_NONE) {
                    o0 = v0; o1 = v1;
                } else {
                    float2 bv = __ldg((const float2*)(bias + col));
                    o0 = v0 + bv.x; o1 = v1 + bv.y;
                    if (epi == EPI2_RELU) {
                        o0 = fmaxf(o0, 0.f); o1 = fmaxf(o1, 0.f);
                    } else {
                        float2 rv = __ldg((const float2*)(resid + rbase + col));
                        o0 += rv.x; o1 += rv.y;
                    }
                }
                *(float2*)(C + rbase + col) = make_float2(o0, o1);
            }
        }
    }
}

// ===========================================================================
extern "C" void kernel_launch(void* const* d_in, const int* in_sizes, int n_in,
                              void* d_out, int out_size)
{
    const float* x_in    = (const float*)d_in[0];
    const float* mass    = (const float*)d_in[1];
    const float* evals   = (const float*)d_in[2];
    const float* evecs   = (const float*)d_in[3];
    const int*   rows    = (const int*)  d_in[4];
    const int*   cols    = (const int*)  d_in[5];
    const float* gradX   = (const float*)d_in[6];
    const float* gradY   = (const float*)d_in[7];
    const float* w_first = (const float*)d_in[8];
    const float* b_first = (const float*)d_in[9];
    const float* dtim    = (const float*)d_in[10];
    const float* A_re    = (const float*)d_in[11];
    const float* A_im    = (const float*)d_in[12];
    const float* mlp_w0  = (const float*)d_in[13];
    const float* mlp_b0  = (const float*)d_in[14];
    const float* mlp_w1  = (const float*)d_in[15];
    const float* mlp_b1  = (const float*)d_in[16];
    const float* mlp_w2  = (const float*)d_in[17];
    const float* mlp_b2  = (const float*)d_in[18];
    const float* w_last  = (const float*)d_in[19];
    const float* b_last  = (const float*)d_in[20];
    float* out = (float*)d_out;

    float *x, *xd, *gX, *gY, *gf, *h1, *h2, *spec, *vxs, *vys;
    unsigned* wimg;
    int *rowptr, *cursor, *perm, *colss;
    cudaGetSymbolAddress((void**)&x,     g_x);
    cudaGetSymbolAddress((void**)&xd,    g_xd);
    cudaGetSymbolAddress((void**)&gX,    g_gX);
    cudaGetSymbolAddress((void**)&gY,    g_gY);
    cudaGetSymbolAddress((void**)&gf,    g_gf);
    cudaGetSymbolAddress((void**)&h1,    g_h1);
    cudaGetSymbolAddress((void**)&h2,    g_h2);
    cudaGetSymbolAddress((void**)&spec,  g_spec);
    cudaGetSymbolAddress((void**)&wimg,  g_wimg);
    cudaGetSymbolAddress((void**)&rowptr, g_rowptr);
    cudaGetSymbolAddress((void**)&cursor, g_cursor);
    cudaGetSymbolAddress((void**)&perm,   g_perm);
    cudaGetSymbolAddress((void**)&colss,  g_colss);
    cudaGetSymbolAddress((void**)&vxs,    g_vxs);
    cudaGetSymbolAddress((void**)&vys,    g_vys);

    const int SMEM_1_64  = 2 * 64 * 272 + 69632;        // 104,448 -> 2 CTA/SM
    const int SMEM_2_128 = 2 * 128 * 272 + 2 * 69632;   // 208,896 -> 1 CTA/SM
    cudaFuncSetAttribute((const void*)gemm_mma<1, 64>,
                         cudaFuncAttributeMaxDynamicSharedMemorySize, SMEM_1_64);
    cudaFuncSetAttribute((const void*)gemm_mma<2, 128>,
                         cudaFuncAttributeMaxDynamicSharedMemorySize, SMEM_2_128);

    const float* nullf = nullptr;

    // ---- one-time preps (cheap; replayed with the graph) ----
    zero_i<<<(N_ + 1 + 255) / 256, 256>>>(rowptr, N_ + 1);
    hist_k<<<(E_ + 255) / 256, 256>>>(rows, rowptr);
    scan_k<<<1, 1024>>>(rowptr);
    cursor_k<<<(N_ + 255) / 256, 256>>>(rowptr, cursor);
    perm_k<<<(E_ + 255) / 256, 256>>>(rows, cursor, perm);
    sortvals_k<<<(E_ + 255) / 256, 256>>>(perm, cols, gradX, gradY, colss, vxs, vys);
    prep_all_w_k<<<36, 256>>>(A_re, A_im, mlp_w0, mlp_w1, mlp_w2, wimg);

    first_k<<<ROWS_TOT / 32, 128>>>(x_in, w_first, b_first, x);

    for (int i = 0; i < 4; i++) {
        // --- spectral diffusion ---
        zero_k<<<64, 256>>>((float4*)spec, B_ * 128 * 128 / 4);
        spec_fwd_k<<<dim3((N_ + 511) / 512, B_), 256>>>(evecs, x, mass, spec, 512);
        prep_spec_k<<<dim3(4, 8), 256>>>(spec, evals, dtim + i * CW_,
                                         wimg + 36 * (long)SLOT_U32);
        gemm_mma<1, 64><<<dim3(N_ / 64, B_), 256, SMEM_1_64>>>(
            evecs, nullf, nullf, wimg, N_, 1, 36, 1, EPI2_NONE,
            nullf, nullf, nullf, nullf, xd);

        // --- sparse gradients (CSR gather, no atomics) ---
        spmm_gather_k<<<dim3(N_ / SG_ROWS, B_), 128>>>(
            rowptr, colss, vxs, vys, xd, gX, gY);

        // --- rotation + tanh gradient features ---
        gemm_mma<2, 128><<<dim3(ROWS_TOT / 128, 1), 256, SMEM_2_128>>>(
            gX, gY, nullf, wimg, ROWS_TOT, 2, i * 9, 0, EPI2_GRAD,
            nullf, nullf, gX, gY, gf);

        // --- MiniMLP + residual ---
        gemm_mma<1, 64><<<dim3(ROWS_TOT / 64, 1), 256, SMEM_1_64>>>(
            x, xd, gf, wimg, ROWS_TOT, 3, i * 9 + 4, 0, EPI2_RELU,
            mlp_b0 + i * CW_, nullf, nullf, nullf, h1);
        gemm_mma<1, 64><<<dim3(ROWS_TOT / 64, 1), 256, SMEM_1_64>>>(
            h1, nullf, nullf, wimg, ROWS_TOT, 1, i * 9 + 7, 0, EPI2_RELU,
            mlp_b1 + i * CW_, nullf, nullf, nullf, h2);
        gemm_mma<1, 64><<<dim3(ROWS_TOT / 64, 1), 256, SMEM_1_64>>>(
            h2, nullf, nullf, wimg, ROWS_TOT, 1, i * 9 + 8, 0, EPI2_RES,
            mlp_b2 + i * CW_, x, nullf, nullf, x);
    }

    last_k<<<ROWS_TOT / 32, 128>>>(x, w_last, b_last, out);
}

// round 9
// speedup vs baseline: 1.6045x; 1.1492x over previous
#include <cuda_runtime.h>
#include <cuda_bf16.h>
#include <math.h>

#define B_   4
#define N_   40000
#define E_   240000
#define CW_  128
#define ROWS_TOT (B_*N_)          // 160000
#define NC   (B_*N_*CW_)

// padded bf16 image: 128 rows x 136 k-cols, 272 B/row
#define IMG_U32 8704              // 34816 B
#define SLOT_U32 (2*IMG_U32)      // hi + lo = 69632 B

// ---- scratch ----
__device__ float g_x  [NC];
__device__ float g_xd [NC];
__device__ float g_gX [NC];
__device__ float g_gY [NC];
__device__ float g_gf [NC];
__device__ float g_h1 [NC];
__device__ float g_h2 [NC];
__device__ float g_spec[B_*128*128];
__device__ unsigned g_wimg[40*SLOT_U32];   // 36 static + 4 spec slots
__device__ int g_rowptr[N_ + 1];
__device__ int g_cursor[N_];
__device__ int g_perm[E_];
__device__ int g_colss[E_];
__device__ float g_vxs[B_*E_];
__device__ float g_vys[B_*E_];

enum { EPI2_NONE = 0, EPI2_RELU = 1, EPI2_RES = 2, EPI2_GRAD = 3 };

// ===========================================================================
// helpers
// ===========================================================================
__device__ __forceinline__ unsigned smem_u32(const void* p) {
    unsigned a;
    asm("{ .reg .u64 t; cvta.to.shared.u64 t, %1; cvt.u32.u64 %0, t; }"
        : "=r"(a) : "l"(p));
    return a;
}
__device__ __forceinline__ void ldsm4(unsigned* r, unsigned addr) {
    asm volatile("ldmatrix.sync.aligned.m8n8.x4.shared.b16 {%0,%1,%2,%3}, [%4];"
                 : "=r"(r[0]), "=r"(r[1]), "=r"(r[2]), "=r"(r[3]) : "r"(addr));
}
__device__ __forceinline__ void ldsm4t(unsigned* r, unsigned addr) {
    asm volatile("ldmatrix.sync.aligned.m8n8.x4.trans.shared.b16 {%0,%1,%2,%3}, [%4];"
                 : "=r"(r[0]), "=r"(r[1]), "=r"(r[2]), "=r"(r[3]) : "r"(addr));
}
__device__ __forceinline__ void mma_bf16(float* c, const unsigned* a,
                                         unsigned b0, unsigned b1) {
    asm volatile(
        "mma.sync.aligned.m16n8k16.row.col.f32.bf16.bf16.f32 "
        "{%0,%1,%2,%3}, {%4,%5,%6,%7}, {%8,%9}, {%0,%1,%2,%3};"
        : "+f"(c[0]), "+f"(c[1]), "+f"(c[2]), "+f"(c[3])
        : "r"(a[0]), "r"(a[1]), "r"(a[2]), "r"(a[3]), "r"(b0), "r"(b1));
}
__device__ __forceinline__ void cp16(unsigned saddr, const void* g) {
    asm volatile("cp.async.cg.shared.global [%0], [%1], 16;"
                 :: "r"(saddr), "l"(g));
}
#define CP_COMMIT() asm volatile("cp.async.commit_group;" ::: "memory")
#define CP_WAIT0()  asm volatile("cp.async.wait_group 0;" ::: "memory")

__device__ __forceinline__ unsigned pack_bf(float a, float b) {
    __nv_bfloat162 t = __floats2bfloat162_rn(a, b);
    return *reinterpret_cast<unsigned*>(&t);
}
__device__ __forceinline__ void split2(float a, float b, unsigned& h, unsigned& l) {
    float ah = __bfloat162float(__float2bfloat16_rn(a));
    float bh = __bfloat162float(__float2bfloat16_rn(b));
    h = pack_bf(a, b);
    l = pack_bf(a - ah, b - bh);
}

// ===========================================================================
// zero
// ===========================================================================
__global__ void zero_k(float4* __restrict__ p, int n4) {
    int i = blockIdx.x * blockDim.x + threadIdx.x;
    if (i < n4) p[i] = make_float4(0.f, 0.f, 0.f, 0.f);
}
__global__ void zero_i(int* __restrict__ p, int n) {
    int i = blockIdx.x * blockDim.x + threadIdx.x;
    if (i < n) p[i] = 0;
}

// ===========================================================================
// CSR build: hist -> scan -> perm -> value presort
// ===========================================================================
__global__ void hist_k(const int* __restrict__ rows, int* __restrict__ rowptr) {
    int e = blockIdx.x * blockDim.x + threadIdx.x;
    if (e < E_) atomicAdd(&rowptr[__ldg(rows + e) + 1], 1);
}
__global__ __launch_bounds__(1024) void scan_k(int* __restrict__ rowptr) {
    __shared__ int sums[1024];
    int t = threadIdx.x;
    const int PER = (N_ + 1023) / 1024;
    int base = 1 + t * PER;
    int s = 0;
    #pragma unroll 4
    for (int i = 0; i < PER; i++) {
        int idx = base + i;
        if (idx <= N_) s += rowptr[idx];
    }
    sums[t] = s;
    __syncthreads();
    for (int off = 1; off < 1024; off <<= 1) {
        int v = (t >= off) ? sums[t - off] : 0;
        __syncthreads();
        sums[t] += v;
        __syncthreads();
    }
    int run = (t > 0) ? sums[t - 1] : 0;
    #pragma unroll 4
    for (int i = 0; i < PER; i++) {
        int idx = base + i;
        if (idx <= N_) {
            run += rowptr[idx];
            rowptr[idx] = run;
        }
    }
    if (t == 0) rowptr[0] = 0;
}
__global__ void cursor_k(const int* __restrict__ rowptr, int* __restrict__ cur) {
    int r = blockIdx.x * blockDim.x + threadIdx.x;
    if (r < N_) cur[r] = rowptr[r];
}
__global__ void perm_k(const int* __restrict__ rows, int* __restrict__ cur,
                       int* __restrict__ perm) {
    int e = blockIdx.x * blockDim.x + threadIdx.x;
    if (e < E_) {
        int pos = atomicAdd(&cur[__ldg(rows + e)], 1);
        perm[pos] = e;
    }
}
__global__ void sortvals_k(const int* __restrict__ perm, const int* __restrict__ cols,
                           const float* __restrict__ gxv, const float* __restrict__ gyv,
                           int* __restrict__ colss, float* __restrict__ vxs,
                           float* __restrict__ vys) {
    int j = blockIdx.x * blockDim.x + threadIdx.x;
    if (j >= E_) return;
    int e = __ldg(perm + j);
    colss[j] = __ldg(cols + e);
    #pragma unroll
    for (int b = 0; b < B_; b++) {
        vxs[b * E_ + j] = __ldg(gxv + (long)b * E_ + e);
        vys[b * E_ + j] = __ldg(gyv + (long)b * E_ + e);
    }
}

// ===========================================================================
// gather SPMM (presorted values, no atomics)
// ===========================================================================
#define SG_ROWS 8
__global__ __launch_bounds__(128) void spmm_gather_k(
    const int* __restrict__ rowptr, const int* __restrict__ colss,
    const float* __restrict__ vxs, const float* __restrict__ vys,
    const float* __restrict__ xd, float* __restrict__ gX, float* __restrict__ gY)
{
    int b = blockIdx.y;
    int c = threadIdx.x;
    int r0 = blockIdx.x * SG_ROWS;
    const float* xb = xd + (long)b * N_ * 128;
    const float* vx = vxs + (long)b * E_;
    const float* vy = vys + (long)b * E_;
    float* oX = gX + (long)b * N_ * 128;
    float* oY = gY + (long)b * N_ * 128;
    #pragma unroll
    for (int rr = 0; rr < SG_ROWS; rr++) {
        int r = r0 + rr;
        int j    = __ldg(rowptr + r);
        int jend = __ldg(rowptr + r + 1);
        float ax = 0.f, ay = 0.f;
        for (; j + 1 < jend; j += 2) {
            int c0 = __ldg(colss + j), c1 = __ldg(colss + j + 1);
            float x0 = __ldg(xb + (long)c0 * 128 + c);
            float x1 = __ldg(xb + (long)c1 * 128 + c);
            ax += __ldg(vx + j) * x0 + __ldg(vx + j + 1) * x1;
            ay += __ldg(vy + j) * x0 + __ldg(vy + j + 1) * x1;
        }
        if (j < jend) {
            int c0 = __ldg(colss + j);
            float x0 = __ldg(xb + (long)c0 * 128 + c);
            ax += __ldg(vx + j) * x0;
            ay += __ldg(vy + j) * x0;
        }
        oX[(long)r * 128 + c] = ax;
        oY[(long)r * 128 + c] = ay;
    }
}

// ===========================================================================
// first / last
// ===========================================================================
__global__ __launch_bounds__(128) void first_k(
    const float* __restrict__ x_in, const float* __restrict__ w,
    const float* __restrict__ bias, float* __restrict__ x)
{
    __shared__ float sW[6 * 128];
    __shared__ float sB[128];
    __shared__ float sX[32 * 6];
    int tid = threadIdx.x;
    long m0 = (long)blockIdx.x * 32;
    for (int idx = tid; idx < 768; idx += 128) sW[idx] = __ldg(w + idx);
    sB[tid] = __ldg(bias + tid);
    for (int idx = tid; idx < 192; idx += 128) sX[idx] = __ldg(x_in + m0 * 6 + idx);
    __syncthreads();
    #pragma unroll 4
    for (int r = 0; r < 32; r++) {
        float a = sB[tid];
        #pragma unroll
        for (int t = 0; t < 6; t++) a += sX[r * 6 + t] * sW[t * 128 + tid];
        x[(m0 + r) * 128 + tid] = a;
    }
}
__global__ __launch_bounds__(128) void last_k(
    const float* __restrict__ x, const float* __restrict__ w,
    const float* __restrict__ bias, float* __restrict__ out)
{
    __shared__ float sX[32 * 128];
    __shared__ float sW[128 * 3];
    __shared__ float sB[3];
    int tid = threadIdx.x;
    long m0 = (long)blockIdx.x * 32;
    for (int idx = tid; idx < 384; idx += 128) sW[idx] = __ldg(w + idx);
    if (tid < 3) sB[tid] = __ldg(bias + tid);
    for (int idx = tid; idx < 1024; idx += 128)
        ((float4*)sX)[idx] = __ldg((const float4*)(x + m0 * 128) + idx);
    __syncthreads();
    if (tid < 96) {
        int r = tid / 3, c = tid % 3;
        float a = sB[c];
        #pragma unroll 8
        for (int k = 0; k < 128; k++) a += sX[r * 128 + k] * sW[k * 3 + c];
        out[(m0 + r) * 3 + c] = a;
    }
}

// ===========================================================================
// spectral forward v2: tensorized, TS=64-row tiles -> 2 CTA/SM
// spec[b][kk][c] += sum_n E[n][kk] * (m*x)[n][c]
// smem: Ehi|Elo|Xhi|Xlo, each 64*272 = 17408 B; total 69632 B
// grid: (79 chunks of 512 rows, B_); 8 tiles of 64 per chunk
// ===========================================================================
#define SF2_SMEM 69632
#define SF2_CHUNK 512
__global__ __launch_bounds__(256, 2) void spec_fwd_mma2(
    const float* __restrict__ evecs, const float* __restrict__ x,
    const float* __restrict__ mass, float* __restrict__ spec)
{
    extern __shared__ char sb[];
    unsigned sbase = smem_u32(sb);
    int tid = threadIdx.x, wid = tid >> 5, lid = tid & 31;
    int b = blockIdx.y;
    int n0 = blockIdx.x * SF2_CHUNK;

    int q = lid >> 3, r = lid & 7;
    int mwarp = wid >> 1, nwarp = wid & 1;
    // trans-A (E^T): (n=(q>>1)*8+r, kk=(q&1)*8)
    int a_n = (q >> 1) * 8 + r, a_kk = (q & 1) * 8;
    // trans-B (X^T): (n=(q&1)*8+r, c=(q>>1)*8)
    int b_n = (q & 1) * 8 + r, b_c = (q >> 1) * 8;

    unsigned aoffb[2], boffb[4];
    #pragma unroll
    for (int mt = 0; mt < 2; mt++)
        aoffb[mt] = (unsigned)(a_n * 272 + (mwarp * 32 + mt * 16 + a_kk) * 2);
    #pragma unroll
    for (int np = 0; np < 4; np++)
        boffb[np] = (unsigned)(b_n * 272 + (nwarp * 64 + np * 16 + b_c) * 2);

    unsigned sEh = sbase,              sEl = sbase + 17408u;
    unsigned sXh = sbase + 2u*17408u,  sXl = sbase + 3u*17408u;

    float acc[2][8][4];
    #pragma unroll
    for (int mt = 0; mt < 2; mt++)
        #pragma unroll
        for (int nt = 0; nt < 8; nt++)
            #pragma unroll
            for (int j = 0; j < 4; j++) acc[mt][nt][j] = 0.f;

    const float* Eb = evecs + (long)b * N_ * 128;
    const float* Xb = x     + (long)b * N_ * 128;
    const float* Mb = mass  + (long)b * N_;

    #pragma unroll 1
    for (int t = 0; t < 8; t++) {
        int tr0 = n0 + t * 64;
        if (tr0 >= N_) break;
        __syncthreads();
        // load + split E and X tiles (64 rows x 128 cols fp32 each)
        #pragma unroll 2
        for (int idx = tid; idx < 2048; idx += 256) {
            int rr = idx >> 5, qq = idx & 31;
            int grow = tr0 + rr;
            float4 e4 = make_float4(0.f, 0.f, 0.f, 0.f);
            float4 x4 = make_float4(0.f, 0.f, 0.f, 0.f);
            if (grow < N_) {
                e4 = __ldg((const float4*)(Eb + (long)grow * 128) + qq);
                x4 = __ldg((const float4*)(Xb + (long)grow * 128) + qq);
                float m = __ldg(Mb + grow);
                x4.x *= m; x4.y *= m; x4.z *= m; x4.w *= m;
            }
            unsigned h0, l0, h1, l1;
            unsigned off = rr * 272 + qq * 8;
            split2(e4.x, e4.y, h0, l0);
            split2(e4.z, e4.w, h1, l1);
            *(uint2*)(sb + off)              = make_uint2(h0, h1);
            *(uint2*)(sb + 17408 + off)      = make_uint2(l0, l1);
            split2(x4.x, x4.y, h0, l0);
            split2(x4.z, x4.w, h1, l1);
            *(uint2*)(sb + 2*17408 + off)    = make_uint2(h0, h1);
            *(uint2*)(sb + 3*17408 + off)    = make_uint2(l0, l1);
        }
        __syncthreads();

        #pragma unroll
        for (int ks = 0; ks < 4; ks++) {
            unsigned kb = ks * 4352u;   // 16 n-rows * 272 B
            unsigned eh[2][4], el[2][4];
            #pragma unroll
            for (int mt = 0; mt < 2; mt++) {
                ldsm4t(eh[mt], sEh + aoffb[mt] + kb);
                ldsm4t(el[mt], sEl + aoffb[mt] + kb);
            }
            #pragma unroll
            for (int np = 0; np < 4; np++) {
                unsigned xh[4], xl[4];
                ldsm4t(xh, sXh + boffb[np] + kb);
                ldsm4t(xl, sXl + boffb[np] + kb);
                #pragma unroll
                for (int mt = 0; mt < 2; mt++) {
                    float* c0 = acc[mt][np * 2];
                    float* c1 = acc[mt][np * 2 + 1];
                    mma_bf16(c0, eh[mt], xh[0], xh[1]);
                    mma_bf16(c0, el[mt], xh[0], xh[1]);
                    mma_bf16(c0, eh[mt], xl[0], xl[1]);
                    mma_bf16(c1, eh[mt], xh[2], xh[3]);
                    mma_bf16(c1, el[mt], xh[2], xh[3]);
                    mma_bf16(c1, eh[mt], xl[2], xl[3]);
                }
            }
        }
    }

    // atomic finish into spec[b]
    float* Sb = spec + (long)b * 16384;
    int colg = (lid & 3) * 2;
    int rowg = lid >> 2;
    #pragma unroll
    for (int mt = 0; mt < 2; mt++)
        #pragma unroll
        for (int h = 0; h < 2; h++) {
            int kk = mwarp * 32 + mt * 16 + rowg + h * 8;
            #pragma unroll
            for (int nt = 0; nt < 8; nt++) {
                int c = nwarp * 64 + nt * 8 + colg;
                atomicAdd(Sb + kk * 128 + c,     acc[mt][nt][h * 2]);
                atomicAdd(Sb + kk * 128 + c + 1, acc[mt][nt][h * 2 + 1]);
            }
        }
}

// ===========================================================================
// W-image preps
// ===========================================================================
__device__ __forceinline__ void prep_w_body(const float* W, float s,
                                            unsigned* hi, unsigned* lo, int tid)
{
    for (int idx = tid; idx < 8192; idx += 256) {
        int n = idx >> 6, kp = idx & 63;
        int k = kp * 2;
        float v0 = __ldg(W + (k + 0) * 128 + n) * s;
        float v1 = __ldg(W + (k + 1) * 128 + n) * s;
        unsigned h, l;
        split2(v0, v1, h, l);
        hi[n * 68 + kp] = h;
        lo[n * 68 + kp] = l;
    }
}
__global__ __launch_bounds__(256) void prep_all_w_k(
    const float* __restrict__ A_re, const float* __restrict__ A_im,
    const float* __restrict__ w0, const float* __restrict__ w1,
    const float* __restrict__ w2, unsigned* __restrict__ wimg)
{
    int s = blockIdx.x;
    int i = s / 9, j = s % 9;
    const float* W;
    float sc = 1.f;
    switch (j) {
        case 0: W = A_re + (long)i * 16384; break;
        case 1: W = A_im + (long)i * 16384; break;
        case 2: W = A_im + (long)i * 16384; sc = -1.f; break;
        case 3: W = A_re + (long)i * 16384; break;
        case 4: W = w0 + (long)i * 49152; break;
        case 5: W = w0 + (long)i * 49152 + 16384; break;
        case 6: W = w0 + (long)i * 49152 + 32768; break;
        case 7: W = w1 + (long)i * 16384; break;
        default: W = w2 + (long)i * 16384; break;
    }
    unsigned* hi = wimg + (long)s * SLOT_U32;
    prep_w_body(W, sc, hi, hi + IMG_U32, threadIdx.x);
}
__global__ __launch_bounds__(256) void prep_spec_k(
    const float* __restrict__ spec, const float* __restrict__ evals,
    const float* __restrict__ dt, unsigned* __restrict__ wimg)
{
    int b = blockIdx.x, part = blockIdx.y;
    const float* W  = spec  + (long)b * 16384;
    const float* ev = evals + b * 128;
    unsigned* hi = wimg + (long)b * SLOT_U32;
    unsigned* lo = hi + IMG_U32;
    int end = (part + 1) * 1024;
    for (int idx = part * 1024 + threadIdx.x; idx < end; idx += 256) {
        int n = idx >> 6, kp = idx & 63;
        int k = kp * 2;
        float d = __ldg(dt + n);
        float v0 = __ldg(W + (k + 0) * 128 + n) * expf(-__ldg(ev + k + 0) * d);
        float v1 = __ldg(W + (k + 1) * 128 + n) * expf(-__ldg(ev + k + 1) * d);
        unsigned h, l;
        split2(v0, v1, h, l);
        hi[n * 68 + kp] = h;
        lo[n * 68 + kp] = l;
    }
}

// ===========================================================================
// mma.sync bf16x3 GEMM, tileable M (TM=64 -> 2 CTA/SM for ND=1)
// ===========================================================================
template <int ND, int TM>
__global__ __launch_bounds__(256, (TM == 64 ? 2 : 1)) void gemm_mma(
    const float* __restrict__ A0, const float* __restrict__ A1,
    const float* __restrict__ A2, const unsigned* __restrict__ wimg,
    int M, int num_in, int slot0, int pbs, int epi,
    const float* __restrict__ bias, const float* __restrict__ resid,
    const float* __restrict__ gXp, const float* __restrict__ gYp,
    float* __restrict__ C)
{
    constexpr int MWN  = (TM == 128) ? 2 : 4;
    constexpr int NCW  = 128 / MWN;
    constexpr int NB   = NCW / 16;
    constexpr unsigned AIMG = TM * 272u;

    extern __shared__ char sb[];
    unsigned sbase = smem_u32(sb);

    int tid = threadIdx.x, wid = tid >> 5, lid = tid & 31;
    int zb = blockIdx.y;
    long aoff = (long)zb * M * 128;
    int m0 = blockIdx.x * TM;

    float acc[ND][2][NB * 2][4];
    #pragma unroll
    for (int d = 0; d < ND; d++)
        #pragma unroll
        for (int mt = 0; mt < 2; mt++)
            #pragma unroll
            for (int nt = 0; nt < NB * 2; nt++)
                #pragma unroll
                for (int j = 0; j < 4; j++) acc[d][mt][nt][j] = 0.f;

    const float* As[3] = {A0, A1, A2};

    int q = lid >> 3, r = lid & 7;
    int mwarp = wid / MWN, nwarp = wid % MWN;
    int a_row_in = (q & 1) * 8 + r;
    int a_koff   = (q >> 1) * 8;
    int b_row_in = (q >> 1) * 8 + r;
    int b_koff   = (q & 1) * 8;

    unsigned sA  = sbase;
    unsigned sAl = sbase + AIMG;
    unsigned sW0 = sbase + 2u * AIMG;

    unsigned aoffb[2], boffb[NB];
    #pragma unroll
    for (int mt = 0; mt < 2; mt++)
        aoffb[mt] = (unsigned)((mwarp * 32 + mt * 16 + a_row_in) * 272 + a_koff * 2);
    #pragma unroll
    for (int np = 0; np < NB; np++)
        boffb[np] = (unsigned)((nwarp * NCW + np * 16 + b_row_in) * 272 + b_koff * 2);

    for (int jin = 0; jin < num_in; jin++) {
        __syncthreads();
        #pragma unroll
        for (int d = 0; d < ND; d++) {
            int slot = slot0 + zb * pbs + jin * ND + d;
            const uint4* src = (const uint4*)(wimg + (long)slot * SLOT_U32);
            unsigned dst = sW0 + d * 69632u;
            #pragma unroll 4
            for (int idx = tid; idx < 4352; idx += 256)
                cp16(dst + idx * 16u, src + idx);
        }
        CP_COMMIT();
        const float* A = As[jin] + aoff;
        #pragma unroll 4
        for (int idx = tid; idx < TM * 32; idx += 256) {
            int rr = idx >> 5, qq = idx & 31;
            int grow = m0 + rr;
            float4 v = make_float4(0.f, 0.f, 0.f, 0.f);
            if (grow < M) v = __ldg((const float4*)(A + (long)grow * 128) + qq);
            unsigned h0, l0, h1, l1;
            split2(v.x, v.y, h0, l0);
            split2(v.z, v.w, h1, l1);
            unsigned off = rr * 272 + qq * 8;
            *(uint2*)(sb + off)        = make_uint2(h0, h1);
            *(uint2*)(sb + AIMG + off) = make_uint2(l0, l1);
        }
        CP_WAIT0();
        __syncthreads();

        #pragma unroll
        for (int ks = 0; ks < 8; ks++) {
            unsigned kb = ks * 32;
            unsigned ah[2][4], al[2][4];
            #pragma unroll
            for (int mt = 0; mt < 2; mt++) {
                ldsm4(ah[mt], sA  + aoffb[mt] + kb);
                ldsm4(al[mt], sAl + aoffb[mt] + kb);
            }
            #pragma unroll
            for (int d = 0; d < ND; d++) {
                unsigned wHi = sW0 + d * 69632u;
                unsigned wLo = wHi + 34816u;
                #pragma unroll
                for (int np = 0; np < NB; np++) {
                    unsigned bh[4], bl[4];
                    ldsm4(bh, wHi + boffb[np] + kb);
                    ldsm4(bl, wLo + boffb[np] + kb);
                    #pragma unroll
                    for (int mt = 0; mt < 2; mt++) {
                        float* c0 = acc[d][mt][np * 2];
                        float* c1 = acc[d][mt][np * 2 + 1];
                        mma_bf16(c0, ah[mt], bh[0], bh[1]);
                        mma_bf16(c0, al[mt], bh[0], bh[1]);
                        mma_bf16(c0, ah[mt], bl[0], bl[1]);
                        mma_bf16(c1, ah[mt], bh[2], bh[3]);
                        mma_bf16(c1, al[mt], bh[2], bh[3]);
                        mma_bf16(c1, ah[mt], bl[2], bl[3]);
                    }
                }
            }
        }
    }

    // epilogue
    int colg = (lid & 3) * 2;
    int rowg = lid >> 2;
    #pragma unroll
    for (int mt = 0; mt < 2; mt++) {
        #pragma unroll
        for (int h = 0; h < 2; h++) {
            int row = m0 + mwarp * 32 + mt * 16 + rowg + h * 8;
            if (row >= M) continue;
            long rbase = aoff + (long)row * 128;
            #pragma unroll
            for (int nt = 0; nt < NB * 2; nt++) {
                int col = nwarp * NCW + nt * 8 + colg;
                float v0 = acc[0][mt][nt][h * 2];
                float v1 = acc[0][mt][nt][h * 2 + 1];
                float o0, o1;
                if (epi == EPI2_GRAD) {
                    float w0 = acc[ND - 1][mt][nt][h * 2];
                    float w1 = acc[ND - 1][mt][nt][h * 2 + 1];
                    float2 gx = __ldg((const float2*)(gXp + rbase + col));
                    float2 gy = __ldg((const float2*)(gYp + rbase + col));
                    o0 = tanhf(gx.x * v0 + gy.x * w0);
                    o1 = tanhf(gx.y * v1 + gy.y * w1);
                } else if (epi == EPI2_NONE) {
                    o0 = v0; o1 = v1;
                } else {
                    float2 bv = __ldg((const float2*)(bias + col));
                    o0 = v0 + bv.x; o1 = v1 + bv.y;
                    if (epi == EPI2_RELU) {
                        o0 = fmaxf(o0, 0.f); o1 = fmaxf(o1, 0.f);
                    } else {
                        float2 rv = __ldg((const float2*)(resid + rbase + col));
                        o0 += rv.x; o1 += rv.y;
                    }
                }
                *(float2*)(C + rbase + col) = make_float2(o0, o1);
            }
        }
    }
}

// ===========================================================================
extern "C" void kernel_launch(void* const* d_in, const int* in_sizes, int n_in,
                              void* d_out, int out_size)
{
    const float* x_in    = (const float*)d_in[0];
    const float* mass    = (const float*)d_in[1];
    const float* evals   = (const float*)d_in[2];
    const float* evecs   = (const float*)d_in[3];
    const int*   rows    = (const int*)  d_in[4];
    const int*   cols    = (const int*)  d_in[5];
    const float* gradX   = (const float*)d_in[6];
    const float* gradY   = (const float*)d_in[7];
    const float* w_first = (const float*)d_in[8];
    const float* b_first = (const float*)d_in[9];
    const float* dtim    = (const float*)d_in[10];
    const float* A_re    = (const float*)d_in[11];
    const float* A_im    = (const float*)d_in[12];
    const float* mlp_w0  = (const float*)d_in[13];
    const float* mlp_b0  = (const float*)d_in[14];
    const float* mlp_w1  = (const float*)d_in[15];
    const float* mlp_b1  = (const float*)d_in[16];
    const float* mlp_w2  = (const float*)d_in[17];
    const float* mlp_b2  = (const float*)d_in[18];
    const float* w_last  = (const float*)d_in[19];
    const float* b_last  = (const float*)d_in[20];
    float* out = (float*)d_out;

    float *x, *xd, *gX, *gY, *gf, *h1, *h2, *spec, *vxs, *vys;
    unsigned* wimg;
    int *rowptr, *cursor, *perm, *colss;
    cudaGetSymbolAddress((void**)&x,     g_x);
    cudaGetSymbolAddress((void**)&xd,    g_xd);
    cudaGetSymbolAddress((void**)&gX,    g_gX);
    cudaGetSymbolAddress((void**)&gY,    g_gY);
    cudaGetSymbolAddress((void**)&gf,    g_gf);
    cudaGetSymbolAddress((void**)&h1,    g_h1);
    cudaGetSymbolAddress((void**)&h2,    g_h2);
    cudaGetSymbolAddress((void**)&spec,  g_spec);
    cudaGetSymbolAddress((void**)&wimg,  g_wimg);
    cudaGetSymbolAddress((void**)&rowptr, g_rowptr);
    cudaGetSymbolAddress((void**)&cursor, g_cursor);
    cudaGetSymbolAddress((void**)&perm,   g_perm);
    cudaGetSymbolAddress((void**)&colss,  g_colss);
    cudaGetSymbolAddress((void**)&vxs,    g_vxs);
    cudaGetSymbolAddress((void**)&vys,    g_vys);

    const int SMEM_1_64  = 2 * 64 * 272 + 69632;        // 104,448 -> 2 CTA/SM
    const int SMEM_2_128 = 2 * 128 * 272 + 2 * 69632;   // 208,896 -> 1 CTA/SM
    cudaFuncSetAttribute((const void*)gemm_mma<1, 64>,
                         cudaFuncAttributeMaxDynamicSharedMemorySize, SMEM_1_64);
    cudaFuncSetAttribute((const void*)gemm_mma<2, 128>,
                         cudaFuncAttributeMaxDynamicSharedMemorySize, SMEM_2_128);
    cudaFuncSetAttribute((const void*)spec_fwd_mma2,
                         cudaFuncAttributeMaxDynamicSharedMemorySize, SF2_SMEM);

    const float* nullf = nullptr;

    // ---- one-time preps ----
    zero_i<<<(N_ + 1 + 255) / 256, 256>>>(rowptr, N_ + 1);
    hist_k<<<(E_ + 255) / 256, 256>>>(rows, rowptr);
    scan_k<<<1, 1024>>>(rowptr);
    cursor_k<<<(N_ + 255) / 256, 256>>>(rowptr, cursor);
    perm_k<<<(E_ + 255) / 256, 256>>>(rows, cursor, perm);
    sortvals_k<<<(E_ + 255) / 256, 256>>>(perm, cols, gradX, gradY, colss, vxs, vys);
    prep_all_w_k<<<36, 256>>>(A_re, A_im, mlp_w0, mlp_w1, mlp_w2, wimg);

    first_k<<<ROWS_TOT / 32, 128>>>(x_in, w_first, b_first, x);

    const int SF2_GRID = (N_ + SF2_CHUNK - 1) / SF2_CHUNK;   // 79

    for (int i = 0; i < 4; i++) {
        // --- spectral diffusion ---
        zero_k<<<64, 256>>>((float4*)spec, B_ * 128 * 128 / 4);
        spec_fwd_mma2<<<dim3(SF2_GRID, B_), 256, SF2_SMEM>>>(evecs, x, mass, spec);
        prep_spec_k<<<dim3(4, 8), 256>>>(spec, evals, dtim + i * CW_,
                                         wimg + 36 * (long)SLOT_U32);
        gemm_mma<1, 64><<<dim3(N_ / 64, B_), 256, SMEM_1_64>>>(
            evecs, nullf, nullf, wimg, N_, 1, 36, 1, EPI2_NONE,
            nullf, nullf, nullf, nullf, xd);

        // --- sparse gradients (CSR gather, no atomics) ---
        spmm_gather_k<<<dim3(N_ / SG_ROWS, B_), 128>>>(
            rowptr, colss, vxs, vys, xd, gX, gY);

        // --- rotation + tanh gradient features ---
        gemm_mma<2, 128><<<dim3(ROWS_TOT / 128, 1), 256, SMEM_2_128>>>(
            gX, gY, nullf, wimg, ROWS_TOT, 2, i * 9, 0, EPI2_GRAD,
            nullf, nullf, gX, gY, gf);

        // --- MiniMLP + residual ---
        gemm_mma<1, 64><<<dim3(ROWS_TOT / 64, 1), 256, SMEM_1_64>>>(
            x, xd, gf, wimg, ROWS_TOT, 3, i * 9 + 4, 0, EPI2_RELU,
            mlp_b0 + i * CW_, nullf, nullf, nullf, h1);
        gemm_mma<1, 64><<<dim3(ROWS_TOT / 64, 1), 256, SMEM_1_64>>>(
            h1, nullf, nullf, wimg, ROWS_TOT, 1, i * 9 + 7, 0, EPI2_RELU,
            mlp_b1 + i * CW_, nullf, nullf, nullf, h2);
        gemm_mma<1, 64><<<dim3(ROWS_TOT / 64, 1), 256, SMEM_1_64>>>(
            h2, nullf, nullf, wimg, ROWS_TOT, 1, i * 9 + 8, 0, EPI2_RES,
            mlp_b2 + i * CW_, x, nullf, nullf, x);
    }

    last_k<<<ROWS_TOT / 32, 128>>>(x, w_last, b_last, out);
}

// round 11
// speedup vs baseline: 2.1969x; 1.3692x over previous
#include <cuda_runtime.h>
#include <cuda_bf16.h>
#include <math.h>

#define B_   4
#define N_   40000
#define E_   240000
#define CW_  128
#define ROWS_TOT (B_*N_)          // 160000
#define NC   (B_*N_*CW_)

// padded bf16 image: rows x 136 k-cols, 272 B/row
#define IMG_U32 8704              // 128-row image: 34816 B
#define SLOT_U32 (2*IMG_U32)      // hi + lo = 69632 B
#define AIMG64 17408u             // 64-row image bytes

// ---- scratch ----
__device__ float g_x  [NC];
__device__ float g_xd [NC];
__device__ float g_gX [NC];
__device__ float g_gY [NC];
__device__ float g_spec[B_*128*128];
__device__ unsigned g_wimg[40*SLOT_U32];   // 36 static + 4 spec slots
__device__ int g_rowptr[N_ + 1];
__device__ int g_cursor[N_];
__device__ int g_perm[E_];
__device__ int g_colss[E_];
__device__ float g_vxs[B_*E_];
__device__ float g_vys[B_*E_];

enum { EPI2_NONE = 0, EPI2_RELU = 1, EPI2_RES = 2, EPI2_GRAD = 3 };

// ===========================================================================
// helpers
// ===========================================================================
__device__ __forceinline__ unsigned smem_u32(const void* p) {
    unsigned a;
    asm("{ .reg .u64 t; cvta.to.shared.u64 t, %1; cvt.u32.u64 %0, t; }"
        : "=r"(a) : "l"(p));
    return a;
}
__device__ __forceinline__ void ldsm4(unsigned* r, unsigned addr) {
    asm volatile("ldmatrix.sync.aligned.m8n8.x4.shared.b16 {%0,%1,%2,%3}, [%4];"
                 : "=r"(r[0]), "=r"(r[1]), "=r"(r[2]), "=r"(r[3]) : "r"(addr));
}
__device__ __forceinline__ void ldsm4t(unsigned* r, unsigned addr) {
    asm volatile("ldmatrix.sync.aligned.m8n8.x4.trans.shared.b16 {%0,%1,%2,%3}, [%4];"
                 : "=r"(r[0]), "=r"(r[1]), "=r"(r[2]), "=r"(r[3]) : "r"(addr));
}
__device__ __forceinline__ void mma_bf16(float* c, const unsigned* a,
                                         unsigned b0, unsigned b1) {
    asm volatile(
        "mma.sync.aligned.m16n8k16.row.col.f32.bf16.bf16.f32 "
        "{%0,%1,%2,%3}, {%4,%5,%6,%7}, {%8,%9}, {%0,%1,%2,%3};"
        : "+f"(c[0]), "+f"(c[1]), "+f"(c[2]), "+f"(c[3])
        : "r"(a[0]), "r"(a[1]), "r"(a[2]), "r"(a[3]), "r"(b0), "r"(b1));
}
__device__ __forceinline__ void cp16(unsigned saddr, const void* g) {
    asm volatile("cp.async.cg.shared.global [%0], [%1], 16;"
                 :: "r"(saddr), "l"(g));
}
#define CP_COMMIT() asm volatile("cp.async.commit_group;" ::: "memory")
#define CP_WAIT0()  asm volatile("cp.async.wait_group 0;" ::: "memory")

__device__ __forceinline__ unsigned pack_bf(float a, float b) {
    __nv_bfloat162 t = __floats2bfloat162_rn(a, b);
    return *reinterpret_cast<unsigned*>(&t);
}
__device__ __forceinline__ void split2(float a, float b, unsigned& h, unsigned& l) {
    float ah = __bfloat162float(__float2bfloat16_rn(a));
    float bh = __bfloat162float(__float2bfloat16_rn(b));
    h = pack_bf(a, b);
    l = pack_bf(a - ah, b - bh);
}

// ===========================================================================
// zero
// ===========================================================================
__global__ void zero_k(float4* __restrict__ p, int n4) {
    int i = blockIdx.x * blockDim.x + threadIdx.x;
    if (i < n4) p[i] = make_float4(0.f, 0.f, 0.f, 0.f);
}
__global__ void zero_i(int* __restrict__ p, int n) {
    int i = blockIdx.x * blockDim.x + threadIdx.x;
    if (i < n) p[i] = 0;
}

// ===========================================================================
// CSR build
// ===========================================================================
__global__ void hist_k(const int* __restrict__ rows, int* __restrict__ rowptr) {
    int e = blockIdx.x * blockDim.x + threadIdx.x;
    if (e < E_) atomicAdd(&rowptr[__ldg(rows + e) + 1], 1);
}
__global__ __launch_bounds__(1024) void scan_k(int* __restrict__ rowptr) {
    __shared__ int sums[1024];
    int t = threadIdx.x;
    const int PER = (N_ + 1023) / 1024;
    int base = 1 + t * PER;
    int s = 0;
    #pragma unroll 4
    for (int i = 0; i < PER; i++) {
        int idx = base + i;
        if (idx <= N_) s += rowptr[idx];
    }
    sums[t] = s;
    __syncthreads();
    for (int off = 1; off < 1024; off <<= 1) {
        int v = (t >= off) ? sums[t - off] : 0;
        __syncthreads();
        sums[t] += v;
        __syncthreads();
    }
    int run = (t > 0) ? sums[t - 1] : 0;
    #pragma unroll 4
    for (int i = 0; i < PER; i++) {
        int idx = base + i;
        if (idx <= N_) {
            run += rowptr[idx];
            rowptr[idx] = run;
        }
    }
    if (t == 0) rowptr[0] = 0;
}
__global__ void cursor_k(const int* __restrict__ rowptr, int* __restrict__ cur) {
    int r = blockIdx.x * blockDim.x + threadIdx.x;
    if (r < N_) cur[r] = rowptr[r];
}
__global__ void perm_k(const int* __restrict__ rows, int* __restrict__ cur,
                       int* __restrict__ perm) {
    int e = blockIdx.x * blockDim.x + threadIdx.x;
    if (e < E_) {
        int pos = atomicAdd(&cur[__ldg(rows + e)], 1);
        perm[pos] = e;
    }
}
__global__ void sortvals_k(const int* __restrict__ perm, const int* __restrict__ cols,
                           const float* __restrict__ gxv, const float* __restrict__ gyv,
                           int* __restrict__ colss, float* __restrict__ vxs,
                           float* __restrict__ vys) {
    int j = blockIdx.x * blockDim.x + threadIdx.x;
    if (j >= E_) return;
    int e = __ldg(perm + j);
    colss[j] = __ldg(cols + e);
    #pragma unroll
    for (int b = 0; b < B_; b++) {
        vxs[b * E_ + j] = __ldg(gxv + (long)b * E_ + e);
        vys[b * E_ + j] = __ldg(gyv + (long)b * E_ + e);
    }
}

// ===========================================================================
// gather SPMM
// ===========================================================================
#define SG_ROWS 8
__global__ __launch_bounds__(128) void spmm_gather_k(
    const int* __restrict__ rowptr, const int* __restrict__ colss,
    const float* __restrict__ vxs, const float* __restrict__ vys,
    const float* __restrict__ xd, float* __restrict__ gX, float* __restrict__ gY)
{
    int b = blockIdx.y;
    int c = threadIdx.x;
    int r0 = blockIdx.x * SG_ROWS;
    const float* xb = xd + (long)b * N_ * 128;
    const float* vx = vxs + (long)b * E_;
    const float* vy = vys + (long)b * E_;
    float* oX = gX + (long)b * N_ * 128;
    float* oY = gY + (long)b * N_ * 128;
    #pragma unroll
    for (int rr = 0; rr < SG_ROWS; rr++) {
        int r = r0 + rr;
        int j    = __ldg(rowptr + r);
        int jend = __ldg(rowptr + r + 1);
        float ax = 0.f, ay = 0.f;
        for (; j + 1 < jend; j += 2) {
            int c0 = __ldg(colss + j), c1 = __ldg(colss + j + 1);
            float x0 = __ldg(xb + (long)c0 * 128 + c);
            float x1 = __ldg(xb + (long)c1 * 128 + c);
            ax += __ldg(vx + j) * x0 + __ldg(vx + j + 1) * x1;
            ay += __ldg(vy + j) * x0 + __ldg(vy + j + 1) * x1;
        }
        if (j < jend) {
            int c0 = __ldg(colss + j);
            float x0 = __ldg(xb + (long)c0 * 128 + c);
            ax += __ldg(vx + j) * x0;
            ay += __ldg(vy + j) * x0;
        }
        oX[(long)r * 128 + c] = ax;
        oY[(long)r * 128 + c] = ay;
    }
}

// ===========================================================================
// first / last
// ===========================================================================
__global__ __launch_bounds__(128) void first_k(
    const float* __restrict__ x_in, const float* __restrict__ w,
    const float* __restrict__ bias, float* __restrict__ x)
{
    __shared__ float sW[6 * 128];
    __shared__ float sB[128];
    __shared__ float sX[32 * 6];
    int tid = threadIdx.x;
    long m0 = (long)blockIdx.x * 32;
    for (int idx = tid; idx < 768; idx += 128) sW[idx] = __ldg(w + idx);
    sB[tid] = __ldg(bias + tid);
    for (int idx = tid; idx < 192; idx += 128) sX[idx] = __ldg(x_in + m0 * 6 + idx);
    __syncthreads();
    #pragma unroll 4
    for (int r = 0; r < 32; r++) {
        float a = sB[tid];
        #pragma unroll
        for (int t = 0; t < 6; t++) a += sX[r * 6 + t] * sW[t * 128 + tid];
        x[(m0 + r) * 128 + tid] = a;
    }
}
__global__ __launch_bounds__(128) void last_k(
    const float* __restrict__ x, const float* __restrict__ w,
    const float* __restrict__ bias, float* __restrict__ out)
{
    __shared__ float sX[32 * 128];
    __shared__ float sW[128 * 3];
    __shared__ float sB[3];
    int tid = threadIdx.x;
    long m0 = (long)blockIdx.x * 32;
    for (int idx = tid; idx < 384; idx += 128) sW[idx] = __ldg(w + idx);
    if (tid < 3) sB[tid] = __ldg(bias + tid);
    for (int idx = tid; idx < 1024; idx += 128)
        ((float4*)sX)[idx] = __ldg((const float4*)(x + m0 * 128) + idx);
    __syncthreads();
    if (tid < 96) {
        int r = tid / 3, c = tid % 3;
        float a = sB[c];
        #pragma unroll 8
        for (int k = 0; k < 128; k++) a += sX[r * 128 + k] * sW[k * 3 + c];
        out[(m0 + r) * 3 + c] = a;
    }
}

// ===========================================================================
// spectral forward v2 (tensorized, 2 CTA/SM) — unchanged from R9
// ===========================================================================
#define SF2_SMEM 69632
#define SF2_CHUNK 512
__global__ __launch_bounds__(256, 2) void spec_fwd_mma2(
    const float* __restrict__ evecs, const float* __restrict__ x,
    const float* __restrict__ mass, float* __restrict__ spec)
{
    extern __shared__ char sb[];
    unsigned sbase = smem_u32(sb);
    int tid = threadIdx.x, wid = tid >> 5, lid = tid & 31;
    int b = blockIdx.y;
    int n0 = blockIdx.x * SF2_CHUNK;

    int q = lid >> 3, r = lid & 7;
    int mwarp = wid >> 1, nwarp = wid & 1;
    int a_n = (q >> 1) * 8 + r, a_kk = (q & 1) * 8;
    int b_n = (q & 1) * 8 + r, b_c = (q >> 1) * 8;

    unsigned aoffb[2], boffb[4];
    #pragma unroll
    for (int mt = 0; mt < 2; mt++)
        aoffb[mt] = (unsigned)(a_n * 272 + (mwarp * 32 + mt * 16 + a_kk) * 2);
    #pragma unroll
    for (int np = 0; np < 4; np++)
        boffb[np] = (unsigned)(b_n * 272 + (nwarp * 64 + np * 16 + b_c) * 2);

    unsigned sEh = sbase,              sEl = sbase + 17408u;
    unsigned sXh = sbase + 2u*17408u,  sXl = sbase + 3u*17408u;

    float acc[2][8][4];
    #pragma unroll
    for (int mt = 0; mt < 2; mt++)
        #pragma unroll
        for (int nt = 0; nt < 8; nt++)
            #pragma unroll
            for (int j = 0; j < 4; j++) acc[mt][nt][j] = 0.f;

    const float* Eb = evecs + (long)b * N_ * 128;
    const float* Xb = x     + (long)b * N_ * 128;
    const float* Mb = mass  + (long)b * N_;

    #pragma unroll 1
    for (int t = 0; t < 8; t++) {
        int tr0 = n0 + t * 64;
        if (tr0 >= N_) break;
        __syncthreads();
        #pragma unroll 2
        for (int idx = tid; idx < 2048; idx += 256) {
            int rr = idx >> 5, qq = idx & 31;
            int grow = tr0 + rr;
            float4 e4 = make_float4(0.f, 0.f, 0.f, 0.f);
            float4 x4 = make_float4(0.f, 0.f, 0.f, 0.f);
            if (grow < N_) {
                e4 = __ldg((const float4*)(Eb + (long)grow * 128) + qq);
                x4 = __ldg((const float4*)(Xb + (long)grow * 128) + qq);
                float m = __ldg(Mb + grow);
                x4.x *= m; x4.y *= m; x4.z *= m; x4.w *= m;
            }
            unsigned h0, l0, h1, l1;
            unsigned off = rr * 272 + qq * 8;
            split2(e4.x, e4.y, h0, l0);
            split2(e4.z, e4.w, h1, l1);
            *(uint2*)(sb + off)              = make_uint2(h0, h1);
            *(uint2*)(sb + 17408 + off)      = make_uint2(l0, l1);
            split2(x4.x, x4.y, h0, l0);
            split2(x4.z, x4.w, h1, l1);
            *(uint2*)(sb + 2*17408 + off)    = make_uint2(h0, h1);
            *(uint2*)(sb + 3*17408 + off)    = make_uint2(l0, l1);
        }
        __syncthreads();

        #pragma unroll
        for (int ks = 0; ks < 4; ks++) {
            unsigned kb = ks * 4352u;
            unsigned eh[2][4], el[2][4];
            #pragma unroll
            for (int mt = 0; mt < 2; mt++) {
                ldsm4t(eh[mt], sEh + aoffb[mt] + kb);
                ldsm4t(el[mt], sEl + aoffb[mt] + kb);
            }
            #pragma unroll
            for (int np = 0; np < 4; np++) {
                unsigned xh[4], xl[4];
                ldsm4t(xh, sXh + boffb[np] + kb);
                ldsm4t(xl, sXl + boffb[np] + kb);
                #pragma unroll
                for (int mt = 0; mt < 2; mt++) {
                    float* c0 = acc[mt][np * 2];
                    float* c1 = acc[mt][np * 2 + 1];
                    mma_bf16(c0, eh[mt], xh[0], xh[1]);
                    mma_bf16(c0, el[mt], xh[0], xh[1]);
                    mma_bf16(c0, eh[mt], xl[0], xl[1]);
                    mma_bf16(c1, eh[mt], xh[2], xh[3]);
                    mma_bf16(c1, el[mt], xh[2], xh[3]);
                    mma_bf16(c1, eh[mt], xl[2], xl[3]);
                }
            }
        }
    }

    float* Sb = spec + (long)b * 16384;
    int colg = (lid & 3) * 2;
    int rowg = lid >> 2;
    #pragma unroll
    for (int mt = 0; mt < 2; mt++)
        #pragma unroll
        for (int h = 0; h < 2; h++) {
            int kk = mwarp * 32 + mt * 16 + rowg + h * 8;
            #pragma unroll
            for (int nt = 0; nt < 8; nt++) {
                int c = nwarp * 64 + nt * 8 + colg;
                atomicAdd(Sb + kk * 128 + c,     acc[mt][nt][h * 2]);
                atomicAdd(Sb + kk * 128 + c + 1, acc[mt][nt][h * 2 + 1]);
            }
        }
}

// ===========================================================================
// W-image preps
// ===========================================================================
__device__ __forceinline__ void prep_w_body(const float* W, float s,
                                            unsigned* hi, unsigned* lo, int tid)
{
    for (int idx = tid; idx < 8192; idx += 256) {
        int n = idx >> 6, kp = idx & 63;
        int k = kp * 2;
        float v0 = __ldg(W + (k + 0) * 128 + n) * s;
        float v1 = __ldg(W + (k + 1) * 128 + n) * s;
        unsigned h, l;
        split2(v0, v1, h, l);
        hi[n * 68 + kp] = h;
        lo[n * 68 + kp] = l;
    }
}
__global__ __launch_bounds__(256) void prep_all_w_k(
    const float* __restrict__ A_re, const float* __restrict__ A_im,
    const float* __restrict__ w0, const float* __restrict__ w1,
    const float* __restrict__ w2, unsigned* __restrict__ wimg)
{
    int s = blockIdx.x;
    int i = s / 9, j = s % 9;
    const float* W;
    float sc = 1.f;
    switch (j) {
        case 0: W = A_re + (long)i * 16384; break;           // gX d0
        case 1: W = A_im + (long)i * 16384; break;           // gX d1
        case 2: W = A_im + (long)i * 16384; sc = -1.f; break; // gY d0
        case 3: W = A_re + (long)i * 16384; break;           // gY d1
        case 4: W = w0 + (long)i * 49152; break;             // mlp0 (x)
        case 5: W = w0 + (long)i * 49152 + 16384; break;     // mlp0 (xd)
        case 6: W = w0 + (long)i * 49152 + 32768; break;     // mlp0 (gf)
        case 7: W = w1 + (long)i * 16384; break;
        default: W = w2 + (long)i * 16384; break;
    }
    unsigned* hi = wimg + (long)s * SLOT_U32;
    prep_w_body(W, sc, hi, hi + IMG_U32, threadIdx.x);
}
__global__ __launch_bounds__(256) void prep_spec_k(
    const float* __restrict__ spec, const float* __restrict__ evals,
    const float* __restrict__ dt, unsigned* __restrict__ wimg)
{
    int b = blockIdx.x, part = blockIdx.y;
    const float* W  = spec  + (long)b * 16384;
    const float* ev = evals + b * 128;
    unsigned* hi = wimg + (long)b * SLOT_U32;
    unsigned* lo = hi + IMG_U32;
    int end = (part + 1) * 1024;
    for (int idx = part * 1024 + threadIdx.x; idx < end; idx += 256) {
        int n = idx >> 6, kp = idx & 63;
        int k = kp * 2;
        float d = __ldg(dt + n);
        float v0 = __ldg(W + (k + 0) * 128 + n) * expf(-__ldg(ev + k + 0) * d);
        float v1 = __ldg(W + (k + 1) * 128 + n) * expf(-__ldg(ev + k + 1) * d);
        unsigned h, l;
        split2(v0, v1, h, l);
        hi[n * 68 + kp] = h;
        lo[n * 68 + kp] = l;
    }
}

// ===========================================================================
// generic GEMM (spec-inv only: ND=1, TM=64, 2 CTA/SM)
// ===========================================================================
__global__ __launch_bounds__(256, 2) void gemm_specinv(
    const float* __restrict__ A0, const unsigned* __restrict__ wimg,
    int slot0, float* __restrict__ C)
{
    extern __shared__ char sb[];
    unsigned sbase = smem_u32(sb);

    int tid = threadIdx.x, wid = tid >> 5, lid = tid & 31;
    int zb = blockIdx.y;
    long aoff = (long)zb * N_ * 128;
    int m0 = blockIdx.x * 64;

    float acc[2][4][4];
    #pragma unroll
    for (int mt = 0; mt < 2; mt++)
        #pragma unroll
        for (int nt = 0; nt < 4; nt++)
            #pragma unroll
            for (int j = 0; j < 4; j++) acc[mt][nt][j] = 0.f;

    int q = lid >> 3, r = lid & 7;
    int mwarp = wid / 4, nwarp = wid % 4;
    int a_row_in = (q & 1) * 8 + r;
    int a_koff   = (q >> 1) * 8;
    int b_row_in = (q >> 1) * 8 + r;
    int b_koff   = (q & 1) * 8;

    unsigned sA  = sbase;
    unsigned sAl = sbase + AIMG64;
    unsigned sW0 = sbase + 2u * AIMG64;

    unsigned aoffb[2], boffb[2];
    #pragma unroll
    for (int mt = 0; mt < 2; mt++)
        aoffb[mt] = (unsigned)((mwarp * 32 + mt * 16 + a_row_in) * 272 + a_koff * 2);
    #pragma unroll
    for (int np = 0; np < 2; np++)
        boffb[np] = (unsigned)((nwarp * 32 + np * 16 + b_row_in) * 272 + b_koff * 2);

    {
        int slot = slot0 + zb;
        const uint4* src = (const uint4*)(wimg + (long)slot * SLOT_U32);
        #pragma unroll 4
        for (int idx = tid; idx < 4352; idx += 256)
            cp16(sW0 + idx * 16u, src + idx);
        CP_COMMIT();
        const float* A = A0 + aoff;
        #pragma unroll 4
        for (int idx = tid; idx < 2048; idx += 256) {
            int rr = idx >> 5, qq = idx & 31;
            float4 v = __ldg((const float4*)(A + (long)(m0 + rr) * 128) + qq);
            unsigned h0, l0, h1, l1;
            split2(v.x, v.y, h0, l0);
            split2(v.z, v.w, h1, l1);
            unsigned off = rr * 272 + qq * 8;
            *(uint2*)(sb + off)          = make_uint2(h0, h1);
            *(uint2*)(sb + AIMG64 + off) = make_uint2(l0, l1);
        }
        CP_WAIT0();
        __syncthreads();

        #pragma unroll
        for (int ks = 0; ks < 8; ks++) {
            unsigned kb = ks * 32;
            unsigned ah[2][4], al[2][4];
            #pragma unroll
            for (int mt = 0; mt < 2; mt++) {
                ldsm4(ah[mt], sA  + aoffb[mt] + kb);
                ldsm4(al[mt], sAl + aoffb[mt] + kb);
            }
            unsigned wLo = sW0 + 34816u;
            #pragma unroll
            for (int np = 0; np < 2; np++) {
                unsigned bh[4], bl[4];
                ldsm4(bh, sW0 + boffb[np] + kb);
                ldsm4(bl, wLo + boffb[np] + kb);
                #pragma unroll
                for (int mt = 0; mt < 2; mt++) {
                    float* c0 = acc[mt][np * 2];
                    float* c1 = acc[mt][np * 2 + 1];
                    mma_bf16(c0, ah[mt], bh[0], bh[1]);
                    mma_bf16(c0, al[mt], bh[0], bh[1]);
                    mma_bf16(c0, ah[mt], bl[0], bl[1]);
                    mma_bf16(c1, ah[mt], bh[2], bh[3]);
                    mma_bf16(c1, al[mt], bh[2], bh[3]);
                    mma_bf16(c1, ah[mt], bl[2], bl[3]);
                }
            }
        }
    }

    int colg = (lid & 3) * 2;
    int rowg = lid >> 2;
    #pragma unroll
    for (int mt = 0; mt < 2; mt++)
        #pragma unroll
        for (int h = 0; h < 2; h++) {
            int row = m0 + mwarp * 32 + mt * 16 + rowg + h * 8;
            long rbase = aoff + (long)row * 128;
            #pragma unroll
            for (int nt = 0; nt < 4; nt++) {
                int col = nwarp * 32 + nt * 8 + colg;
                *(float2*)(C + rbase + col) =
                    make_float2(acc[mt][nt][h * 2], acc[mt][nt][h * 2 + 1]);
            }
        }
}

// ===========================================================================
// FUSED: rotation + tanh gradfeat + mlp0/1/2 + residual, per 64-row tile.
// smem: sAh(17408) | sAl(17408) | sW(69632) = 104448 -> 2 CTA/SM
// ===========================================================================
struct FusedCtx {
    char* sb;
    unsigned sA, sAl, sW;
    unsigned aoffb[2], boffb[2];
    int tid, mwarp, nwarp, rowg, colg;
    long m0;
};

__device__ __forceinline__ void f_copyW(const FusedCtx& c,
                                        const unsigned* wimg, int slot) {
    const uint4* src = (const uint4*)(wimg + (long)slot * SLOT_U32);
    #pragma unroll 4
    for (int idx = c.tid; idx < 4352; idx += 256)
        cp16(c.sW + idx * 16u, src + idx);
    CP_COMMIT();
}
__device__ __forceinline__ void f_loadA(const FusedCtx& c, const float* A) {
    #pragma unroll 4
    for (int idx = c.tid; idx < 2048; idx += 256) {
        int rr = idx >> 5, qq = idx & 31;
        float4 v = __ldg((const float4*)(A + (c.m0 + rr) * 128) + qq);
        unsigned h0, l0, h1, l1;
        split2(v.x, v.y, h0, l0);
        split2(v.z, v.w, h1, l1);
        unsigned off = rr * 272 + qq * 8;
        *(uint2*)(c.sb + off)          = make_uint2(h0, h1);
        *(uint2*)(c.sb + AIMG64 + off) = make_uint2(l0, l1);
    }
}
__device__ __forceinline__ void f_mma(const FusedCtx& c, float acc[2][4][4]) {
    unsigned wLo = c.sW + 34816u;
    #pragma unroll
    for (int ks = 0; ks < 8; ks++) {
        unsigned kb = ks * 32;
        unsigned ah[2][4], al[2][4];
        #pragma unroll
        for (int mt = 0; mt < 2; mt++) {
            ldsm4(ah[mt], c.sA  + c.aoffb[mt] + kb);
            ldsm4(al[mt], c.sAl + c.aoffb[mt] + kb);
        }
        #pragma unroll
        for (int np = 0; np < 2; np++) {
            unsigned bh[4], bl[4];
            ldsm4(bh, c.sW + c.boffb[np] + kb);
            ldsm4(bl, wLo  + c.boffb[np] + kb);
            #pragma unroll
            for (int mt = 0; mt < 2; mt++) {
                float* c0 = acc[mt][np * 2];
                float* c1 = acc[mt][np * 2 + 1];
                mma_bf16(c0, ah[mt], bh[0], bh[1]);
                mma_bf16(c0, al[mt], bh[0], bh[1]);
                mma_bf16(c0, ah[mt], bl[0], bl[1]);
                mma_bf16(c1, ah[mt], bh[2], bh[3]);
                mma_bf16(c1, al[mt], bh[2], bh[3]);
                mma_bf16(c1, ah[mt], bl[2], bl[3]);
            }
        }
    }
}
// write (v0, v1) epilogue values back into the A image (bf16 hi/lo)
__device__ __forceinline__ void f_store_img(const FusedCtx& c, int row_in, int col,
                                            float v0, float v1) {
    unsigned h, l;
    split2(v0, v1, h, l);
    unsigned off = row_in * 272 + col * 2;
    *(unsigned*)(c.sb + off)          = h;
    *(unsigned*)(c.sb + AIMG64 + off) = l;
}

__global__ __launch_bounds__(256, 2) void fused_mlp_k(
    const float* __restrict__ gX, const float* __restrict__ gY,
    const float* __restrict__ xd, const unsigned* __restrict__ wimg,
    int slot0, const float* __restrict__ b0, const float* __restrict__ b1,
    const float* __restrict__ b2, float* __restrict__ x)
{
    extern __shared__ char sb[];
    FusedCtx c;
    c.sb = sb;
    unsigned sbase = smem_u32(sb);
    c.sA = sbase; c.sAl = sbase + AIMG64; c.sW = sbase + 2u * AIMG64;
    c.tid = threadIdx.x;
    int wid = c.tid >> 5, lid = c.tid & 31;
    c.mwarp = wid / 4; c.nwarp = wid % 4;
    c.rowg = lid >> 2; c.colg = (lid & 3) * 2;
    c.m0 = (long)blockIdx.x * 64;

    int q = lid >> 3, r = lid & 7;
    int a_row_in = (q & 1) * 8 + r, a_koff = (q >> 1) * 8;
    int b_row_in = (q >> 1) * 8 + r, b_koff = (q & 1) * 8;
    #pragma unroll
    for (int mt = 0; mt < 2; mt++)
        c.aoffb[mt] = (unsigned)((c.mwarp * 32 + mt * 16 + a_row_in) * 272 + a_koff * 2);
    #pragma unroll
    for (int np = 0; np < 2; np++)
        c.boffb[np] = (unsigned)((c.nwarp * 32 + np * 16 + b_row_in) * 272 + b_koff * 2);

    // ---------- rotation: Breal (d0), Bimag (d1) ----------
    float accR[2][2][4][4];
    #pragma unroll
    for (int d = 0; d < 2; d++)
        #pragma unroll
        for (int mt = 0; mt < 2; mt++)
            #pragma unroll
            for (int nt = 0; nt < 4; nt++)
                #pragma unroll
                for (int j = 0; j < 4; j++) accR[d][mt][nt][j] = 0.f;

    #pragma unroll
    for (int jin = 0; jin < 2; jin++) {
        const float* src = (jin == 0) ? gX : gY;
        __syncthreads();
        f_copyW(c, wimg, slot0 + jin * 2);
        f_loadA(c, src);
        CP_WAIT0();
        __syncthreads();
        f_mma(c, accR[0]);
        __syncthreads();
        f_copyW(c, wimg, slot0 + jin * 2 + 1);
        CP_WAIT0();
        __syncthreads();
        f_mma(c, accR[1]);
    }

    // ---------- grad epilogue -> gf image ----------
    __syncthreads();
    #pragma unroll
    for (int mt = 0; mt < 2; mt++)
        #pragma unroll
        for (int h = 0; h < 2; h++) {
            int rin = c.mwarp * 32 + mt * 16 + c.rowg + h * 8;
            long rbase = (c.m0 + rin) * 128;
            #pragma unroll
            for (int nt = 0; nt < 4; nt++) {
                int col = c.nwarp * 32 + nt * 8 + c.colg;
                float2 gx = __ldg((const float2*)(gX + rbase + col));
                float2 gy = __ldg((const float2*)(gY + rbase + col));
                float v0 = tanhf(gx.x * accR[0][mt][nt][h * 2]
                               + gy.x * accR[1][mt][nt][h * 2]);
                float v1 = tanhf(gx.y * accR[0][mt][nt][h * 2 + 1]
                               + gy.y * accR[1][mt][nt][h * 2 + 1]);
                f_store_img(c, rin, col, v0, v1);
            }
        }

    // ---------- mlp0: gf (in image), then x, then xd ----------
    float acc[2][4][4];
    #pragma unroll
    for (int mt = 0; mt < 2; mt++)
        #pragma unroll
        for (int nt = 0; nt < 4; nt++)
            #pragma unroll
            for (int j = 0; j < 4; j++) acc[mt][nt][j] = 0.f;

    __syncthreads();
    f_copyW(c, wimg, slot0 + 6);
    CP_WAIT0();
    __syncthreads();
    f_mma(c, acc);

    __syncthreads();
    f_copyW(c, wimg, slot0 + 4);
    f_loadA(c, x);
    CP_WAIT0();
    __syncthreads();
    f_mma(c, acc);

    __syncthreads();
    f_copyW(c, wimg, slot0 + 5);
    f_loadA(c, xd);
    CP_WAIT0();
    __syncthreads();
    f_mma(c, acc);

    // h1 = relu(acc + b0)  -> image
    __syncthreads();
    #pragma unroll
    for (int mt = 0; mt < 2; mt++)
        #pragma unroll
        for (int h = 0; h < 2; h++) {
            int rin = c.mwarp * 32 + mt * 16 + c.rowg + h * 8;
            #pragma unroll
            for (int nt = 0; nt < 4; nt++) {
                int col = c.nwarp * 32 + nt * 8 + c.colg;
                float2 bv = __ldg((const float2*)(b0 + col));
                float v0 = fmaxf(acc[mt][nt][h * 2] + bv.x, 0.f);
                float v1 = fmaxf(acc[mt][nt][h * 2 + 1] + bv.y, 0.f);
                f_store_img(c, rin, col, v0, v1);
                acc[mt][nt][h * 2] = 0.f;
                acc[mt][nt][h * 2 + 1] = 0.f;
            }
        }

    // ---------- mlp1 ----------
    __syncthreads();
    f_copyW(c, wimg, slot0 + 7);
    CP_WAIT0();
    __syncthreads();
    f_mma(c, acc);

    __syncthreads();
    #pragma unroll
    for (int mt = 0; mt < 2; mt++)
        #pragma unroll
        for (int h = 0; h < 2; h++) {
            int rin = c.mwarp * 32 + mt * 16 + c.rowg + h * 8;
            #pragma unroll
            for (int nt = 0; nt < 4; nt++) {
                int col = c.nwarp * 32 + nt * 8 + c.colg;
                float2 bv = __ldg((const float2*)(b1 + col));
                float v0 = fmaxf(acc[mt][nt][h * 2] + bv.x, 0.f);
                float v1 = fmaxf(acc[mt][nt][h * 2 + 1] + bv.y, 0.f);
                f_store_img(c, rin, col, v0, v1);
                acc[mt][nt][h * 2] = 0.f;
                acc[mt][nt][h * 2 + 1] = 0.f;
            }
        }

    // ---------- mlp2 + residual -> x ----------
    __syncthreads();
    f_copyW(c, wimg, slot0 + 8);
    CP_WAIT0();
    __syncthreads();
    f_mma(c, acc);

    #pragma unroll
    for (int mt = 0; mt < 2; mt++)
        #pragma unroll
        for (int h = 0; h < 2; h++) {
            int rin = c.mwarp * 32 + mt * 16 + c.rowg + h * 8;
            long rbase = (c.m0 + rin) * 128;
            #pragma unroll
            for (int nt = 0; nt < 4; nt++) {
                int col = c.nwarp * 32 + nt * 8 + c.colg;
                float2 bv = __ldg((const float2*)(b2 + col));
                float2 rv = __ldg((const float2*)(x + rbase + col));
                *(float2*)(x + rbase + col) =
                    make_float2(acc[mt][nt][h * 2] + bv.x + rv.x,
                                acc[mt][nt][h * 2 + 1] + bv.y + rv.y);
            }
        }
}

// ===========================================================================
extern "C" void kernel_launch(void* const* d_in, const int* in_sizes, int n_in,
                              void* d_out, int out_size)
{
    const float* x_in    = (const float*)d_in[0];
    const float* mass    = (const float*)d_in[1];
    const float* evals   = (const float*)d_in[2];
    const float* evecs   = (const float*)d_in[3];
    const int*   rows    = (const int*)  d_in[4];
    const int*   cols    = (const int*)  d_in[5];
    const float* gradX   = (const float*)d_in[6];
    const float* gradY   = (const float*)d_in[7];
    const float* w_first = (const float*)d_in[8];
    const float* b_first = (const float*)d_in[9];
    const float* dtim    = (const float*)d_in[10];
    const float* A_re    = (const float*)d_in[11];
    const float* A_im    = (const float*)d_in[12];
    const float* mlp_w0  = (const float*)d_in[13];
    const float* mlp_b0  = (const float*)d_in[14];
    const float* mlp_w1  = (const float*)d_in[15];
    const float* mlp_b1  = (const float*)d_in[16];
    const float* mlp_w2  = (const float*)d_in[17];
    const float* mlp_b2  = (const float*)d_in[18];
    const float* w_last  = (const float*)d_in[19];
    const float* b_last  = (const float*)d_in[20];
    float* out = (float*)d_out;

    float *x, *xd, *gX, *gY, *spec, *vxs, *vys;
    unsigned* wimg;
    int *rowptr, *cursor, *perm, *colss;
    cudaGetSymbolAddress((void**)&x,     g_x);
    cudaGetSymbolAddress((void**)&xd,    g_xd);
    cudaGetSymbolAddress((void**)&gX,    g_gX);
    cudaGetSymbolAddress((void**)&gY,    g_gY);
    cudaGetSymbolAddress((void**)&spec,  g_spec);
    cudaGetSymbolAddress((void**)&wimg,  g_wimg);
    cudaGetSymbolAddress((void**)&rowptr, g_rowptr);
    cudaGetSymbolAddress((void**)&cursor, g_cursor);
    cudaGetSymbolAddress((void**)&perm,   g_perm);
    cudaGetSymbolAddress((void**)&colss,  g_colss);
    cudaGetSymbolAddress((void**)&vxs,    g_vxs);
    cudaGetSymbolAddress((void**)&vys,    g_vys);

    const int SMEM64 = 2 * 17408 + 69632;   // 104,448 -> 2 CTA/SM
    cudaFuncSetAttribute((const void*)gemm_specinv,
                         cudaFuncAttributeMaxDynamicSharedMemorySize, SMEM64);
    cudaFuncSetAttribute((const void*)fused_mlp_k,
                         cudaFuncAttributeMaxDynamicSharedMemorySize, SMEM64);
    cudaFuncSetAttribute((const void*)spec_fwd_mma2,
                         cudaFuncAttributeMaxDynamicSharedMemorySize, SF2_SMEM);

    // ---- one-time preps ----
    zero_i<<<(N_ + 1 + 255) / 256, 256>>>(rowptr, N_ + 1);
    hist_k<<<(E_ + 255) / 256, 256>>>(rows, rowptr);
    scan_k<<<1, 1024>>>(rowptr);
    cursor_k<<<(N_ + 255) / 256, 256>>>(rowptr, cursor);
    perm_k<<<(E_ + 255) / 256, 256>>>(rows, cursor, perm);
    sortvals_k<<<(E_ + 255) / 256, 256>>>(perm, cols, gradX, gradY, colss, vxs, vys);
    prep_all_w_k<<<36, 256>>>(A_re, A_im, mlp_w0, mlp_w1, mlp_w2, wimg);

    first_k<<<ROWS_TOT / 32, 128>>>(x_in, w_first, b_first, x);

    const int SF2_GRID = (N_ + SF2_CHUNK - 1) / SF2_CHUNK;   // 79

    for (int i = 0; i < 4; i++) {
        // --- spectral diffusion ---
        zero_k<<<64, 256>>>((float4*)spec, B_ * 128 * 128 / 4);
        spec_fwd_mma2<<<dim3(SF2_GRID, B_), 256, SF2_SMEM>>>(evecs, x, mass, spec);
        prep_spec_k<<<dim3(4, 8), 256>>>(spec, evals, dtim + i * CW_,
                                         wimg + 36 * (long)SLOT_U32);
        gemm_specinv<<<dim3(N_ / 64, B_), 256, SMEM64>>>(evecs, wimg, 36, xd);

        // --- sparse gradients (CSR gather) ---
        spmm_gather_k<<<dim3(N_ / SG_ROWS, B_), 128>>>(
            rowptr, colss, vxs, vys, xd, gX, gY);

        // --- rotation + gradfeat + MLP + residual (single fused kernel) ---
        fused_mlp_k<<<ROWS_TOT / 64, 256, SMEM64>>>(
            gX, gY, xd, wimg, i * 9,
            mlp_b0 + i * CW_, mlp_b1 + i * CW_, mlp_b2 + i * CW_, x);
    }

    last_k<<<ROWS_TOT / 32, 128>>>(x, w_last, b_last, out);
}